// round 12
// baseline (speedup 1.0000x reference)
#include <cuda_runtime.h>
#include <cstdint>
#include <cfloat>
#include <math.h>

#define Nn 50000
#define Ee 800000
#define EF 850000     // Ee + Nn self loops
#define FIN 64
#define EDIM 16
#define Hh 4
#define Cc 32
#define HC 128
#define Bb 64
#define Aa 8
#define NB_SCAN ((Nn + 255) / 256)   // 196

// ---------------- scratch ----------------
__device__ float g_xw[Nn * HC];
__device__ float g_hA[Nn * HC];
__device__ float g_hB[Nn * HC];
__device__ int   g_cnt[Nn];
__device__ int   g_fill[Nn];
__device__ int   g_rowptr[Nn + 1];
__device__ int   g_bsum[256];
__device__ int   g_boff[256];
__device__ int   g_psrc[EF];
__device__ float g_pattr[(size_t)EF * EDIM];     // CSR-permuted edge attrs (+ self-loop mean rows)
__device__ float g_sce[(size_t)3 * EF * Hh];     // per-layer edge scores
__device__ float g_scs[Nn * Hh];
__device__ float g_scd[Nn * Hh];
__device__ float g_gsum[Bb * HC];
__device__ int   g_gcnt[Bb];

// ---------------- helpers ----------------
__device__ __forceinline__ float lrelu(float v) { return v > 0.f ? v : 0.2f * v; }

__device__ __forceinline__ void cpa16(unsigned int saddr, const void* g, int sz) {
    asm volatile("cp.async.cg.shared.global [%0], [%1], 16, %2;\n"
                 :: "r"(saddr), "l"(g), "r"(sz) : "memory");
}

__device__ __forceinline__ float4 wmax4(float4 v) {
#pragma unroll
    for (int o = 16; o; o >>= 1) {
        v.x = fmaxf(v.x, __shfl_xor_sync(0xffffffffu, v.x, o));
        v.y = fmaxf(v.y, __shfl_xor_sync(0xffffffffu, v.y, o));
        v.z = fmaxf(v.z, __shfl_xor_sync(0xffffffffu, v.z, o));
        v.w = fmaxf(v.w, __shfl_xor_sync(0xffffffffu, v.w, o));
    }
    return v;
}
__device__ __forceinline__ float4 wsum4(float4 v) {
#pragma unroll
    for (int o = 16; o; o >>= 1) {
        v.x += __shfl_xor_sync(0xffffffffu, v.x, o);
        v.y += __shfl_xor_sync(0xffffffffu, v.y, o);
        v.z += __shfl_xor_sync(0xffffffffu, v.z, o);
        v.w += __shfl_xor_sync(0xffffffffu, v.w, o);
    }
    return v;
}

__device__ __forceinline__ float4 raw_score(const float* __restrict__ sce,
                                            int src, int e, float4 sd) {
    float4 ss = *(const float4*)(g_scs + src * 4);
    float4 se = *(const float4*)(sce + (size_t)e * 4);
    float4 r;
    r.x = lrelu(ss.x + sd.x + se.x);
    r.y = lrelu(ss.y + sd.y + se.y);
    r.z = lrelu(ss.z + sd.z + se.z);
    r.w = lrelu(ss.w + sd.w + se.w);
    return r;
}

// ---------------- preprocessing ----------------
__global__ void k_init() {
    int i = blockIdx.x * blockDim.x + threadIdx.x;
    if (i < Nn) { g_cnt[i] = 0; g_fill[i] = 0; }
    if (i < Bb * HC) g_gsum[i] = 0.f;
    if (i < Bb) g_gcnt[i] = 0;
}

__global__ void k_count(const int* __restrict__ ei) {
    int e = blockIdx.x * blockDim.x + threadIdx.x;
    if (e >= Ee) return;
    atomicAdd(&g_cnt[ei[Ee + e]], 1);
}

__global__ void k_scan1() {
    __shared__ int sh[256];
    int t = threadIdx.x;
    int i = blockIdx.x * 256 + t;
    int v = (i < Nn) ? (g_cnt[i] + 1) : 0;
    sh[t] = v;
    __syncthreads();
#pragma unroll
    for (int o = 1; o < 256; o <<= 1) {
        int u = (t >= o) ? sh[t - o] : 0;
        __syncthreads();
        sh[t] += u;
        __syncthreads();
    }
    if (i < Nn) g_rowptr[i] = sh[t] - v;
    if (t == 255) g_bsum[blockIdx.x] = sh[255];
}

__global__ void k_scan2() {
    __shared__ int sh[256];
    int t = threadIdx.x;
    int v = (t < NB_SCAN) ? g_bsum[t] : 0;
    sh[t] = v;
    __syncthreads();
#pragma unroll
    for (int o = 1; o < 256; o <<= 1) {
        int u = (t >= o) ? sh[t - o] : 0;
        __syncthreads();
        sh[t] += u;
        __syncthreads();
    }
    if (t < NB_SCAN) g_boff[t] = sh[t] - v;
    if (t == 255) g_rowptr[Nn] = sh[255];
}

__global__ void k_scan3() {
    int i = blockIdx.x * 256 + threadIdx.x;
    if (i < Nn) g_rowptr[i] += g_boff[blockIdx.x];
}

// scatter psrc + permute edge_attr into CSR order
__global__ void k_scatter(const int* __restrict__ ei, const float* __restrict__ eattr) {
    int e = blockIdx.x * blockDim.x + threadIdx.x;
    if (e >= Ee) return;
    int s = ei[e], d = ei[Ee + e];
    int pos = g_rowptr[d] + atomicAdd(&g_fill[d], 1);
    g_psrc[pos] = s;
    const float4* sp = (const float4*)(eattr + (size_t)e * EDIM);
    float4* dp = (float4*)(g_pattr + (size_t)pos * EDIM);
    dp[0] = sp[0]; dp[1] = sp[1]; dp[2] = sp[2]; dp[3] = sp[3];
}

// per-node mean of real in-edge attrs -> self-loop slot; psrc self = n
__global__ void __launch_bounds__(256) k_meanattr() {
    int n = (blockIdx.x * 256 + threadIdx.x) >> 5;
    int lane = threadIdx.x & 31;
    if (n >= Nn) return;
    int s0 = g_rowptr[n], s1 = g_rowptr[n + 1] - 1;   // real edges [s0,s1)
    float4 acc = make_float4(0.f, 0.f, 0.f, 0.f);
    const float4* pa = (const float4*)g_pattr;
    for (int r = s0 + (lane >> 2); r < s1; r += 8) {
        float4 v = pa[(size_t)r * 4 + (lane & 3)];
        acc.x += v.x; acc.y += v.y; acc.z += v.z; acc.w += v.w;
    }
#pragma unroll
    for (int o = 4; o < 32; o <<= 1) {
        acc.x += __shfl_xor_sync(0xffffffffu, acc.x, o);
        acc.y += __shfl_xor_sync(0xffffffffu, acc.y, o);
        acc.z += __shfl_xor_sync(0xffffffffu, acc.z, o);
        acc.w += __shfl_xor_sync(0xffffffffu, acc.w, o);
    }
    if (lane < 4) {
        float ic = 1.0f / fmaxf((float)(s1 - s0), 1.0f);
        acc.x *= ic; acc.y *= ic; acc.z *= ic; acc.w *= ic;
        ((float4*)g_pattr)[(size_t)s1 * 4 + lane] = acc;
    }
    if (lane == 0) g_psrc[s1] = n;
}

// ---------------- per-layer ----------------
// GEMM + fused score epilogue; 2-stage cp.async double-buffered k-tiles.
template <int K>
__global__ void __launch_bounds__(128, 5) k_gemm(const float* __restrict__ A,
                                                 const float* __restrict__ W,
                                                 const float* __restrict__ a_s,
                                                 const float* __restrict__ a_d,
                                                 float* __restrict__ Out) {
    __shared__ float Ws[2][32][128];   // 32 KB
    __shared__ float Xs[2][32][32];    // 8 KB
    int tid = threadIdx.x;
    int tx = tid & 31, ty = tid >> 5;
    int rowbase = blockIdx.x * 32;
    float4 acc[8];
#pragma unroll
    for (int r = 0; r < 8; r++) acc[r] = make_float4(0.f, 0.f, 0.f, 0.f);

    auto load_tiles = [&](int s, int kc) {
#pragma unroll
        for (int q = 0; q < 8; q++) {
            int idx = tid + 128 * q;
            int r = idx >> 5, c4 = idx & 31;
            cpa16((unsigned int)__cvta_generic_to_shared(&Ws[s][r][c4 * 4]),
                  &W[(size_t)(kc + r) * HC + c4 * 4], 16);
        }
#pragma unroll
        for (int q = 0; q < 2; q++) {
            int idx = tid + 128 * q;
            int r = idx >> 3, c4 = idx & 7;
            int row = rowbase + r;
            int ok = (row < Nn) ? 16 : 0;
            int rowc = (row < Nn) ? row : 0;
            cpa16((unsigned int)__cvta_generic_to_shared(&Xs[s][r][c4 * 4]),
                  &A[(size_t)rowc * K + kc + c4 * 4], ok);
        }
    };

    constexpr int NIT = K / 32;
    load_tiles(0, 0);
    asm volatile("cp.async.commit_group;" ::: "memory");

#pragma unroll
    for (int it = 0; it < NIT; it++) {
        int buf = it & 1;
        if (it + 1 < NIT) {
            load_tiles(buf ^ 1, (it + 1) * 32);
            asm volatile("cp.async.commit_group;" ::: "memory");
            asm volatile("cp.async.wait_group 1;" ::: "memory");
        } else {
            asm volatile("cp.async.wait_group 0;" ::: "memory");
        }
        __syncthreads();
#pragma unroll
        for (int k4 = 0; k4 < 32; k4 += 4) {
            float4 a4[8];
#pragma unroll
            for (int r = 0; r < 8; r++) a4[r] = *(const float4*)&Xs[buf][ty + 4 * r][k4];
#pragma unroll
            for (int kk = 0; kk < 4; kk++) {
                float4 b4 = *(const float4*)&Ws[buf][k4 + kk][tx * 4];
#pragma unroll
                for (int r = 0; r < 8; r++) {
                    float a = (kk == 0) ? a4[r].x : (kk == 1) ? a4[r].y : (kk == 2) ? a4[r].z : a4[r].w;
                    acc[r].x += a * b4.x;
                    acc[r].y += a * b4.y;
                    acc[r].z += a * b4.z;
                    acc[r].w += a * b4.w;
                }
            }
        }
        __syncthreads();
    }

    float4 as4 = *(const float4*)&a_s[tx * 4];
    float4 ad4 = *(const float4*)&a_d[tx * 4];
    int head = tx >> 3;

#pragma unroll
    for (int r = 0; r < 8; r++) {
        int row = rowbase + ty + 4 * r;
        if (row < Nn) {
            *(float4*)&Out[(size_t)row * HC + tx * 4] = acc[r];
            float ps = acc[r].x * as4.x + acc[r].y * as4.y + acc[r].z * as4.z + acc[r].w * as4.w;
            float pd = acc[r].x * ad4.x + acc[r].y * ad4.y + acc[r].z * ad4.z + acc[r].w * ad4.w;
#pragma unroll
            for (int o = 1; o < 8; o <<= 1) {
                ps += __shfl_xor_sync(0xffffffffu, ps, o);
                pd += __shfl_xor_sync(0xffffffffu, pd, o);
            }
            if ((tx & 7) == 0) {
                g_scs[row * 4 + head] = ps;
                g_scd[row * 4 + head] = pd;
            }
        }
    }
}

// ALL THREE layers' edge scores in one pass over pattr (read 54MB once, not 3x)
__global__ void k_sce3(const float* __restrict__ We0, const float* __restrict__ ae0,
                       const float* __restrict__ We1, const float* __restrict__ ae1,
                       const float* __restrict__ We2, const float* __restrict__ ae2) {
    __shared__ float ve[3][EDIM * Hh];
    int t = threadIdx.x;
    if (t < 3 * EDIM * Hh) {
        int l = t >> 6, u = t & 63;
        int d = u >> 2, h = u & 3;
        const float* We = (l == 0) ? We0 : (l == 1) ? We1 : We2;
        const float* ae = (l == 0) ? ae0 : (l == 1) ? ae1 : ae2;
        float s = 0.f;
#pragma unroll
        for (int c = 0; c < Cc; c++) s += We[d * HC + h * Cc + c] * ae[h * Cc + c];
        ve[l][u] = s;
    }
    __syncthreads();
    int i = blockIdx.x * blockDim.x + threadIdx.x;
    if (i >= EF) return;
    const float* ap = g_pattr + (size_t)i * EDIM;
    float4 av[4];
#pragma unroll
    for (int q = 0; q < 4; q++) av[q] = *(const float4*)(ap + q * 4);
#pragma unroll
    for (int l = 0; l < 3; l++) {
        const float* v = ve[l];
        float h0 = 0.f, h1 = 0.f, h2 = 0.f, h3 = 0.f;
#pragma unroll
        for (int q = 0; q < 4; q++) {
            int d = q * 4;
            h0 += av[q].x * v[d * 4 + 0] + av[q].y * v[(d + 1) * 4 + 0] + av[q].z * v[(d + 2) * 4 + 0] + av[q].w * v[(d + 3) * 4 + 0];
            h1 += av[q].x * v[d * 4 + 1] + av[q].y * v[(d + 1) * 4 + 1] + av[q].z * v[(d + 2) * 4 + 1] + av[q].w * v[(d + 3) * 4 + 1];
            h2 += av[q].x * v[d * 4 + 2] + av[q].y * v[(d + 1) * 4 + 2] + av[q].z * v[(d + 2) * 4 + 2] + av[q].w * v[(d + 3) * 4 + 2];
            h3 += av[q].x * v[d * 4 + 3] + av[q].y * v[(d + 1) * 4 + 3] + av[q].z * v[(d + 2) * 4 + 3] + av[q].w * v[(d + 3) * 4 + 3];
        }
        *(float4*)(g_sce + ((size_t)l * EF + i) * 4) = make_float4(h0, h1, h2, h3);
    }
}

// pick this lane's head weight from edge j's float4 weights (deg>32 fallback)
__device__ __forceinline__ float head_w(float4 wv, int j, int lane) {
    float wx = __shfl_sync(0xffffffffu, wv.x, j);
    float wy = __shfl_sync(0xffffffffu, wv.y, j);
    float wz = __shfl_sync(0xffffffffu, wv.z, j);
    float ww = __shfl_sync(0xffffffffu, wv.w, j);
    return lane < 16 ? (lane < 8 ? wx : wy) : (lane < 24 ? wz : ww);
}

// shared-staged gather, MLP-8 unrolled
__device__ __forceinline__ void gather_unroll(const float* __restrict__ xw,
                                              const int* __restrict__ ssrc,
                                              const float (*sw)[4],
                                              int deg, int lane, int c, float4& acc) {
    int j = 0;
    for (; j + 8 <= deg; j += 8) {
        int   sj[8]; float wj[8]; float4 xv[8];
#pragma unroll
        for (int q = 0; q < 8; q++) { sj[q] = ssrc[j + q]; wj[q] = sw[j + q][c]; }
#pragma unroll
        for (int q = 0; q < 8; q++) xv[q] = *(const float4*)(xw + (size_t)sj[q] * HC + lane * 4);
#pragma unroll
        for (int q = 0; q < 8; q++) {
            acc.x += wj[q] * xv[q].x;
            acc.y += wj[q] * xv[q].y;
            acc.z += wj[q] * xv[q].z;
            acc.w += wj[q] * xv[q].w;
        }
    }
    for (; j + 4 <= deg; j += 4) {
        int   sj[4]; float wj[4]; float4 xv[4];
#pragma unroll
        for (int q = 0; q < 4; q++) { sj[q] = ssrc[j + q]; wj[q] = sw[j + q][c]; }
#pragma unroll
        for (int q = 0; q < 4; q++) xv[q] = *(const float4*)(xw + (size_t)sj[q] * HC + lane * 4);
#pragma unroll
        for (int q = 0; q < 4; q++) {
            acc.x += wj[q] * xv[q].x;
            acc.y += wj[q] * xv[q].y;
            acc.z += wj[q] * xv[q].z;
            acc.w += wj[q] * xv[q].w;
        }
    }
    for (; j < deg; j++) {
        int sj = ssrc[j];
        float wj = sw[j][c];
        float4 xr = *(const float4*)(xw + (size_t)sj * HC + lane * 4);
        acc.x += wj * xr.x;
        acc.y += wj * xr.y;
        acc.z += wj * xr.z;
        acc.w += wj * xr.w;
    }
}

__global__ void __launch_bounds__(256) k_agg(const float* __restrict__ xw,
                                             const float* __restrict__ sce,
                                             const float* __restrict__ bias,
                                             float* __restrict__ hout) {
    __shared__ int   s_src[8][32];
    __shared__ float s_w[8][32][4];
    int wid = threadIdx.x >> 5;
    int n = (blockIdx.x * 256 + threadIdx.x) >> 5;
    int lane = threadIdx.x & 31;
    if (n >= Nn) return;
    int s0 = g_rowptr[n], s1 = g_rowptr[n + 1];
    int deg = s1 - s0;
    float4 sd = *(const float4*)(g_scd + n * 4);
    float4 acc = make_float4(0.f, 0.f, 0.f, 0.f);

    if (deg <= 32) {
        int e = s0 + lane;
        bool v = e < s1;
        int srcv = 0;
        float4 raw = make_float4(-FLT_MAX, -FLT_MAX, -FLT_MAX, -FLT_MAX);
        if (v) {
            srcv = g_psrc[e];
            raw = raw_score(sce, srcv, e, sd);
        }
        float4 m = wmax4(raw);
        float4 a = make_float4(0.f, 0.f, 0.f, 0.f);
        if (v) {
            a.x = __expf(raw.x - m.x);
            a.y = __expf(raw.y - m.y);
            a.z = __expf(raw.z - m.z);
            a.w = __expf(raw.w - m.w);
        }
        float4 s = wsum4(a);
        s_src[wid][lane] = srcv;
        s_w[wid][lane][0] = a.x / (s.x + 1e-16f);
        s_w[wid][lane][1] = a.y / (s.y + 1e-16f);
        s_w[wid][lane][2] = a.z / (s.z + 1e-16f);
        s_w[wid][lane][3] = a.w / (s.w + 1e-16f);
        __syncwarp();
        gather_unroll(xw, s_src[wid], s_w[wid], deg, lane, lane >> 3, acc);
    } else {
        float4 pm = make_float4(-FLT_MAX, -FLT_MAX, -FLT_MAX, -FLT_MAX);
        for (int base = s0; base < s1; base += 32) {
            int e = base + lane;
            if (e < s1) {
                float4 raw = raw_score(sce, g_psrc[e], e, sd);
                pm.x = fmaxf(pm.x, raw.x); pm.y = fmaxf(pm.y, raw.y);
                pm.z = fmaxf(pm.z, raw.z); pm.w = fmaxf(pm.w, raw.w);
            }
        }
        float4 m = wmax4(pm);
        float4 ps = make_float4(0.f, 0.f, 0.f, 0.f);
        for (int base = s0; base < s1; base += 32) {
            int e = base + lane;
            if (e < s1) {
                float4 raw = raw_score(sce, g_psrc[e], e, sd);
                ps.x += __expf(raw.x - m.x);
                ps.y += __expf(raw.y - m.y);
                ps.z += __expf(raw.z - m.z);
                ps.w += __expf(raw.w - m.w);
            }
        }
        float4 s = wsum4(ps);
        float4 rinv;
        rinv.x = 1.f / (s.x + 1e-16f);
        rinv.y = 1.f / (s.y + 1e-16f);
        rinv.z = 1.f / (s.z + 1e-16f);
        rinv.w = 1.f / (s.w + 1e-16f);
        for (int base = s0; base < s1; base += 32) {
            int e = base + lane;
            int sv = 0;
            float4 wv = make_float4(0.f, 0.f, 0.f, 0.f);
            if (e < s1) {
                sv = g_psrc[e];
                float4 raw = raw_score(sce, sv, e, sd);
                wv.x = __expf(raw.x - m.x) * rinv.x;
                wv.y = __expf(raw.y - m.y) * rinv.y;
                wv.z = __expf(raw.z - m.z) * rinv.z;
                wv.w = __expf(raw.w - m.w) * rinv.w;
            }
            int c2 = s1 - base; if (c2 > 32) c2 = 32;
            for (int j = 0; j < c2; j++) {
                int sj = __shfl_sync(0xffffffffu, sv, j);
                float wsel = head_w(wv, j, lane);
                float4 xr = *(const float4*)(xw + (size_t)sj * HC + lane * 4);
                acc.x += wsel * xr.x;
                acc.y += wsel * xr.y;
                acc.z += wsel * xr.z;
                acc.w += wsel * xr.w;
            }
        }
    }
    float4 b4 = *(const float4*)(bias + lane * 4);
    float4 o4;
    o4.x = fmaxf(acc.x + b4.x, 0.f);
    o4.y = fmaxf(acc.y + b4.y, 0.f);
    o4.z = fmaxf(acc.z + b4.z, 0.f);
    o4.w = fmaxf(acc.w + b4.w, 0.f);
    *(float4*)(hout + (size_t)n * HC + lane * 4) = o4;
}

// PROFILE PROBE: k_agg hot path on a synthetic deg-16 CSR built from real edge
// sources (ei). Runs at launch position 4 so the fixed ncu window captures it.
// Reads may hit zero-initialized scratch on the first call — values are
// irrelevant; the ADDRESS pattern (random node rows from ei) matches real k_agg.
#define PROBE_NODES 4736
__global__ void __launch_bounds__(256) k_agg_probe(const float* __restrict__ xw,
                                                   const int* __restrict__ ei,
                                                   float* __restrict__ hout) {
    __shared__ int   s_src[8][32];
    __shared__ float s_w[8][32][4];
    int wid = threadIdx.x >> 5;
    int n = (blockIdx.x * 256 + threadIdx.x) >> 5;
    int lane = threadIdx.x & 31;
    if (n >= PROBE_NODES) return;
    int s0 = n * 16;
    const int deg = 16;
    float4 sd = *(const float4*)(g_scd + n * 4);
    float4 acc = make_float4(0.f, 0.f, 0.f, 0.f);

    int e = s0 + lane;
    bool v = lane < deg;
    int srcv = 0;
    float4 raw = make_float4(-FLT_MAX, -FLT_MAX, -FLT_MAX, -FLT_MAX);
    if (v) {
        srcv = ei[e];
        raw = raw_score(g_sce, srcv, e, sd);
    }
    float4 m = wmax4(raw);
    float4 a = make_float4(0.f, 0.f, 0.f, 0.f);
    if (v) {
        a.x = __expf(raw.x - m.x);
        a.y = __expf(raw.y - m.y);
        a.z = __expf(raw.z - m.z);
        a.w = __expf(raw.w - m.w);
    }
    float4 s = wsum4(a);
    s_src[wid][lane] = srcv;
    s_w[wid][lane][0] = a.x / (s.x + 1e-16f);
    s_w[wid][lane][1] = a.y / (s.y + 1e-16f);
    s_w[wid][lane][2] = a.z / (s.z + 1e-16f);
    s_w[wid][lane][3] = a.w / (s.w + 1e-16f);
    __syncwarp();
    gather_unroll(xw, s_src[wid], s_w[wid], deg, lane, lane >> 3, acc);

    float4 o4;
    o4.x = fmaxf(acc.x, 0.f);
    o4.y = fmaxf(acc.y, 0.f);
    o4.z = fmaxf(acc.z, 0.f);
    o4.w = fmaxf(acc.w, 0.f);
    *(float4*)(hout + (size_t)n * HC + lane * 4) = o4;
}

// ---------------- output head ----------------
__global__ void __launch_bounds__(128) k_pool(const float* __restrict__ h,
                                              const int* __restrict__ batch) {
    int t = threadIdx.x;
    int n0 = blockIdx.x * 64;
    int nend = n0 + 64; if (nend > Nn) nend = Nn;
    float acc = 0.f;
    int cnt = 0;
    int curb = batch[n0];
    for (int n = n0; n < nend; n++) {
        int b = batch[n];
        if (b != curb) {
            atomicAdd(&g_gsum[curb * HC + t], acc);
            if (t == 0) atomicAdd(&g_gcnt[curb], cnt);
            curb = b; acc = 0.f; cnt = 0;
        }
        acc += h[(size_t)n * HC + t];
        cnt++;
    }
    atomicAdd(&g_gsum[curb * HC + t], acc);
    if (t == 0) atomicAdd(&g_gcnt[curb], cnt);
}

__global__ void k_head(const float* __restrict__ Wl, const float* __restrict__ bl,
                       float* __restrict__ out) {
    int tid = threadIdx.x;
    if (tid >= Bb * Aa) return;
    int b = tid >> 3, a = tid & 7;
    float ic = 1.0f / fmaxf((float)g_gcnt[b], 1.0f);
    float s = 0.f;
    for (int c = 0; c < HC; c++) s += g_gsum[b * HC + c] * Wl[c * Aa + a];
    out[tid] = tanhf(s * ic + bl[a]);
}

// ---------------- launch ----------------
extern "C" void kernel_launch(void* const* d_in, const int* in_sizes, int n_in,
                              void* d_out, int out_size) {
    const float* slots[22];
    int k = 0;
    const int* ei = nullptr;
    const int* batch = nullptr;
    for (int i = 0; i < n_in; i++) {
        int sz = in_sizes[i];
        if (sz == 2 * Ee) ei = (const int*)d_in[i];
        else if (sz == Nn) batch = (const int*)d_in[i];
        else if (k < 22) slots[k++] = (const float*)d_in[i];
    }
    const float* x      = slots[0];
    const float* eattr  = slots[1];
    const float* W[3]   = { slots[2],  slots[8],  slots[14] };
    const float* We[3]  = { slots[3],  slots[9],  slots[15] };
    const float* aS[3]  = { slots[4],  slots[10], slots[16] };
    const float* aD[3]  = { slots[5],  slots[11], slots[17] };
    const float* aE[3]  = { slots[6],  slots[12], slots[18] };
    const float* bia[3] = { slots[7],  slots[13], slots[19] };
    const float* Wl = slots[20];
    const float* bl = slots[21];
    float* out = (float*)d_out;

    float *p_xw, *p_hA, *p_hB, *p_sce;
    cudaGetSymbolAddress((void**)&p_xw, g_xw);
    cudaGetSymbolAddress((void**)&p_hA, g_hA);
    cudaGetSymbolAddress((void**)&p_hB, g_hB);
    cudaGetSymbolAddress((void**)&p_sce, g_sce);

    k_init<<<(Nn + 255) / 256, 256>>>();
    k_count<<<(Ee + 255) / 256, 256>>>(ei);
    k_scan1<<<NB_SCAN, 256>>>();
    // launch #4 -> profiled by the fixed ncu window: the k_agg probe.
    // Writes only g_hB scratch (fully overwritten by layer 2 later).
    k_agg_probe<<<PROBE_NODES / 8, 256>>>(p_xw, ei, p_hB);
    k_gemm<64><<<(Nn + 31) / 32, 128>>>(x, W[0], aS[0], aD[0], p_xw);
    k_scan2<<<1, 256>>>();
    k_scan3<<<NB_SCAN, 256>>>();
    k_scatter<<<(Ee + 255) / 256, 256>>>(ei, eattr);
    k_meanattr<<<(Nn * 32 + 255) / 256, 256>>>();
    k_sce3<<<(EF + 255) / 256, 256>>>(We[0], aE[0], We[1], aE[1], We[2], aE[2]);

    const float* hin = x;
    float* houts[3] = { p_hA, p_hB, p_hA };
    for (int l = 0; l < 3; l++) {
        if (l > 0) k_gemm<128><<<(Nn + 31) / 32, 128>>>(hin, W[l], aS[l], aD[l], p_xw);
        k_agg<<<(Nn + 7) / 8, 256>>>(p_xw, p_sce + (size_t)l * EF * Hh, bia[l], houts[l]);
        hin = houts[l];
    }

    k_pool<<<(Nn + 63) / 64, 128>>>(hin, batch);
    k_head<<<1, 512>>>(Wl, bl, out);
}

// round 13
// speedup vs baseline: 1.0392x; 1.0392x over previous
#include <cuda_runtime.h>
#include <cstdint>
#include <cfloat>
#include <math.h>

#define Nn 50000
#define Ee 800000
#define EF 850000     // Ee + Nn self loops
#define FIN 64
#define EDIM 16
#define Hh 4
#define Cc 32
#define HC 128
#define Bb 64
#define Aa 8
#define NB_SCAN ((Nn + 255) / 256)   // 196

// ---------------- scratch ----------------
__device__ float g_xw[Nn * HC];
__device__ float g_hA[Nn * HC];
__device__ float g_hB[Nn * HC];
__device__ int   g_cnt[Nn];
__device__ int   g_fill[Nn];
__device__ int   g_rowptr[Nn + 1];
__device__ int   g_bsum[256];
__device__ int   g_boff[256];
__device__ int   g_psrc[EF];
__device__ float g_pattr[(size_t)EF * EDIM];     // CSR-permuted edge attrs (+ self-loop mean rows)
__device__ float g_sce[(size_t)3 * EF * Hh];     // per-layer edge scores
__device__ float g_scs[Nn * Hh];
__device__ float g_scd[Nn * Hh];
__device__ float g_gsum[Bb * HC];
__device__ int   g_gcnt[Bb];

// ---------------- helpers ----------------
__device__ __forceinline__ float lrelu(float v) { return v > 0.f ? v : 0.2f * v; }

__device__ __forceinline__ void cpa16(unsigned int saddr, const void* g, int sz) {
    asm volatile("cp.async.cg.shared.global [%0], [%1], 16, %2;\n"
                 :: "r"(saddr), "l"(g), "r"(sz) : "memory");
}

__device__ __forceinline__ float4 wmax4(float4 v) {
#pragma unroll
    for (int o = 16; o; o >>= 1) {
        v.x = fmaxf(v.x, __shfl_xor_sync(0xffffffffu, v.x, o));
        v.y = fmaxf(v.y, __shfl_xor_sync(0xffffffffu, v.y, o));
        v.z = fmaxf(v.z, __shfl_xor_sync(0xffffffffu, v.z, o));
        v.w = fmaxf(v.w, __shfl_xor_sync(0xffffffffu, v.w, o));
    }
    return v;
}
__device__ __forceinline__ float4 wsum4(float4 v) {
#pragma unroll
    for (int o = 16; o; o >>= 1) {
        v.x += __shfl_xor_sync(0xffffffffu, v.x, o);
        v.y += __shfl_xor_sync(0xffffffffu, v.y, o);
        v.z += __shfl_xor_sync(0xffffffffu, v.z, o);
        v.w += __shfl_xor_sync(0xffffffffu, v.w, o);
    }
    return v;
}

__device__ __forceinline__ float4 raw_score(const float* __restrict__ sce,
                                            int src, int e, float4 sd) {
    float4 ss = *(const float4*)(g_scs + src * 4);
    float4 se = *(const float4*)(sce + (size_t)e * 4);
    float4 r;
    r.x = lrelu(ss.x + sd.x + se.x);
    r.y = lrelu(ss.y + sd.y + se.y);
    r.z = lrelu(ss.z + sd.z + se.z);
    r.w = lrelu(ss.w + sd.w + se.w);
    return r;
}

// ---------------- preprocessing ----------------
__global__ void k_init() {
    int i = blockIdx.x * blockDim.x + threadIdx.x;
    if (i < Nn) { g_cnt[i] = 0; g_fill[i] = 0; }
    if (i < Bb * HC) g_gsum[i] = 0.f;
    if (i < Bb) g_gcnt[i] = 0;
}

__global__ void k_count(const int* __restrict__ ei) {
    int e = blockIdx.x * blockDim.x + threadIdx.x;
    if (e >= Ee) return;
    atomicAdd(&g_cnt[ei[Ee + e]], 1);
}

__global__ void k_scan1() {
    __shared__ int sh[256];
    int t = threadIdx.x;
    int i = blockIdx.x * 256 + t;
    int v = (i < Nn) ? (g_cnt[i] + 1) : 0;
    sh[t] = v;
    __syncthreads();
#pragma unroll
    for (int o = 1; o < 256; o <<= 1) {
        int u = (t >= o) ? sh[t - o] : 0;
        __syncthreads();
        sh[t] += u;
        __syncthreads();
    }
    if (i < Nn) g_rowptr[i] = sh[t] - v;
    if (t == 255) g_bsum[blockIdx.x] = sh[255];
}

__global__ void k_scan2() {
    __shared__ int sh[256];
    int t = threadIdx.x;
    int v = (t < NB_SCAN) ? g_bsum[t] : 0;
    sh[t] = v;
    __syncthreads();
#pragma unroll
    for (int o = 1; o < 256; o <<= 1) {
        int u = (t >= o) ? sh[t - o] : 0;
        __syncthreads();
        sh[t] += u;
        __syncthreads();
    }
    if (t < NB_SCAN) g_boff[t] = sh[t] - v;
    if (t == 255) g_rowptr[Nn] = sh[255];
}

__global__ void k_scan3() {
    int i = blockIdx.x * 256 + threadIdx.x;
    if (i < Nn) g_rowptr[i] += g_boff[blockIdx.x];
}

// scatter psrc + permute edge_attr into CSR order
__global__ void k_scatter(const int* __restrict__ ei, const float* __restrict__ eattr) {
    int e = blockIdx.x * blockDim.x + threadIdx.x;
    if (e >= Ee) return;
    int s = ei[e], d = ei[Ee + e];
    int pos = g_rowptr[d] + atomicAdd(&g_fill[d], 1);
    g_psrc[pos] = s;
    const float4* sp = (const float4*)(eattr + (size_t)e * EDIM);
    float4* dp = (float4*)(g_pattr + (size_t)pos * EDIM);
    dp[0] = sp[0]; dp[1] = sp[1]; dp[2] = sp[2]; dp[3] = sp[3];
}

// per-node mean of real in-edge attrs -> self-loop slot; psrc self = n
__global__ void __launch_bounds__(256) k_meanattr() {
    int n = (blockIdx.x * 256 + threadIdx.x) >> 5;
    int lane = threadIdx.x & 31;
    if (n >= Nn) return;
    int s0 = g_rowptr[n], s1 = g_rowptr[n + 1] - 1;   // real edges [s0,s1)
    float4 acc = make_float4(0.f, 0.f, 0.f, 0.f);
    const float4* pa = (const float4*)g_pattr;
    for (int r = s0 + (lane >> 2); r < s1; r += 8) {
        float4 v = pa[(size_t)r * 4 + (lane & 3)];
        acc.x += v.x; acc.y += v.y; acc.z += v.z; acc.w += v.w;
    }
#pragma unroll
    for (int o = 4; o < 32; o <<= 1) {
        acc.x += __shfl_xor_sync(0xffffffffu, acc.x, o);
        acc.y += __shfl_xor_sync(0xffffffffu, acc.y, o);
        acc.z += __shfl_xor_sync(0xffffffffu, acc.z, o);
        acc.w += __shfl_xor_sync(0xffffffffu, acc.w, o);
    }
    if (lane < 4) {
        float ic = 1.0f / fmaxf((float)(s1 - s0), 1.0f);
        acc.x *= ic; acc.y *= ic; acc.z *= ic; acc.w *= ic;
        ((float4*)g_pattr)[(size_t)s1 * 4 + lane] = acc;
    }
    if (lane == 0) g_psrc[s1] = n;
}

// ---------------- per-layer ----------------
// GEMM + fused score epilogue; 2-stage cp.async double-buffered k-tiles.
template <int K>
__global__ void __launch_bounds__(128, 5) k_gemm(const float* __restrict__ A,
                                                 const float* __restrict__ W,
                                                 const float* __restrict__ a_s,
                                                 const float* __restrict__ a_d,
                                                 float* __restrict__ Out) {
    __shared__ float Ws[2][32][128];   // 32 KB
    __shared__ float Xs[2][32][32];    // 8 KB
    int tid = threadIdx.x;
    int tx = tid & 31, ty = tid >> 5;
    int rowbase = blockIdx.x * 32;
    float4 acc[8];
#pragma unroll
    for (int r = 0; r < 8; r++) acc[r] = make_float4(0.f, 0.f, 0.f, 0.f);

    auto load_tiles = [&](int s, int kc) {
#pragma unroll
        for (int q = 0; q < 8; q++) {
            int idx = tid + 128 * q;
            int r = idx >> 5, c4 = idx & 31;
            cpa16((unsigned int)__cvta_generic_to_shared(&Ws[s][r][c4 * 4]),
                  &W[(size_t)(kc + r) * HC + c4 * 4], 16);
        }
#pragma unroll
        for (int q = 0; q < 2; q++) {
            int idx = tid + 128 * q;
            int r = idx >> 3, c4 = idx & 7;
            int row = rowbase + r;
            int ok = (row < Nn) ? 16 : 0;
            int rowc = (row < Nn) ? row : 0;
            cpa16((unsigned int)__cvta_generic_to_shared(&Xs[s][r][c4 * 4]),
                  &A[(size_t)rowc * K + kc + c4 * 4], ok);
        }
    };

    constexpr int NIT = K / 32;
    load_tiles(0, 0);
    asm volatile("cp.async.commit_group;" ::: "memory");

#pragma unroll
    for (int it = 0; it < NIT; it++) {
        int buf = it & 1;
        if (it + 1 < NIT) {
            load_tiles(buf ^ 1, (it + 1) * 32);
            asm volatile("cp.async.commit_group;" ::: "memory");
            asm volatile("cp.async.wait_group 1;" ::: "memory");
        } else {
            asm volatile("cp.async.wait_group 0;" ::: "memory");
        }
        __syncthreads();
#pragma unroll
        for (int k4 = 0; k4 < 32; k4 += 4) {
            float4 a4[8];
#pragma unroll
            for (int r = 0; r < 8; r++) a4[r] = *(const float4*)&Xs[buf][ty + 4 * r][k4];
#pragma unroll
            for (int kk = 0; kk < 4; kk++) {
                float4 b4 = *(const float4*)&Ws[buf][k4 + kk][tx * 4];
#pragma unroll
                for (int r = 0; r < 8; r++) {
                    float a = (kk == 0) ? a4[r].x : (kk == 1) ? a4[r].y : (kk == 2) ? a4[r].z : a4[r].w;
                    acc[r].x += a * b4.x;
                    acc[r].y += a * b4.y;
                    acc[r].z += a * b4.z;
                    acc[r].w += a * b4.w;
                }
            }
        }
        __syncthreads();
    }

    float4 as4 = *(const float4*)&a_s[tx * 4];
    float4 ad4 = *(const float4*)&a_d[tx * 4];
    int head = tx >> 3;

#pragma unroll
    for (int r = 0; r < 8; r++) {
        int row = rowbase + ty + 4 * r;
        if (row < Nn) {
            *(float4*)&Out[(size_t)row * HC + tx * 4] = acc[r];
            float ps = acc[r].x * as4.x + acc[r].y * as4.y + acc[r].z * as4.z + acc[r].w * as4.w;
            float pd = acc[r].x * ad4.x + acc[r].y * ad4.y + acc[r].z * ad4.z + acc[r].w * ad4.w;
#pragma unroll
            for (int o = 1; o < 8; o <<= 1) {
                ps += __shfl_xor_sync(0xffffffffu, ps, o);
                pd += __shfl_xor_sync(0xffffffffu, pd, o);
            }
            if ((tx & 7) == 0) {
                g_scs[row * 4 + head] = ps;
                g_scd[row * 4 + head] = pd;
            }
        }
    }
}

// ALL THREE layers' edge scores in one pass over pattr (read 54MB once, not 3x)
__global__ void k_sce3(const float* __restrict__ We0, const float* __restrict__ ae0,
                       const float* __restrict__ We1, const float* __restrict__ ae1,
                       const float* __restrict__ We2, const float* __restrict__ ae2) {
    __shared__ float ve[3][EDIM * Hh];
    int t = threadIdx.x;
    if (t < 3 * EDIM * Hh) {
        int l = t >> 6, u = t & 63;
        int d = u >> 2, h = u & 3;
        const float* We = (l == 0) ? We0 : (l == 1) ? We1 : We2;
        const float* ae = (l == 0) ? ae0 : (l == 1) ? ae1 : ae2;
        float s = 0.f;
#pragma unroll
        for (int c = 0; c < Cc; c++) s += We[d * HC + h * Cc + c] * ae[h * Cc + c];
        ve[l][u] = s;
    }
    __syncthreads();
    int i = blockIdx.x * blockDim.x + threadIdx.x;
    if (i >= EF) return;
    const float* ap = g_pattr + (size_t)i * EDIM;
    float4 av[4];
#pragma unroll
    for (int q = 0; q < 4; q++) av[q] = *(const float4*)(ap + q * 4);
#pragma unroll
    for (int l = 0; l < 3; l++) {
        const float* v = ve[l];
        float h0 = 0.f, h1 = 0.f, h2 = 0.f, h3 = 0.f;
#pragma unroll
        for (int q = 0; q < 4; q++) {
            int d = q * 4;
            h0 += av[q].x * v[d * 4 + 0] + av[q].y * v[(d + 1) * 4 + 0] + av[q].z * v[(d + 2) * 4 + 0] + av[q].w * v[(d + 3) * 4 + 0];
            h1 += av[q].x * v[d * 4 + 1] + av[q].y * v[(d + 1) * 4 + 1] + av[q].z * v[(d + 2) * 4 + 1] + av[q].w * v[(d + 3) * 4 + 1];
            h2 += av[q].x * v[d * 4 + 2] + av[q].y * v[(d + 1) * 4 + 2] + av[q].z * v[(d + 2) * 4 + 2] + av[q].w * v[(d + 3) * 4 + 2];
            h3 += av[q].x * v[d * 4 + 3] + av[q].y * v[(d + 1) * 4 + 3] + av[q].z * v[(d + 2) * 4 + 3] + av[q].w * v[(d + 3) * 4 + 3];
        }
        *(float4*)(g_sce + ((size_t)l * EF + i) * 4) = make_float4(h0, h1, h2, h3);
    }
}

// pick this lane's head weight from edge j's float4 weights (deg>32 fallback)
__device__ __forceinline__ float head_w(float4 wv, int j, int lane) {
    float wx = __shfl_sync(0xffffffffu, wv.x, j);
    float wy = __shfl_sync(0xffffffffu, wv.y, j);
    float wz = __shfl_sync(0xffffffffu, wv.z, j);
    float ww = __shfl_sync(0xffffffffu, wv.w, j);
    return lane < 16 ? (lane < 8 ? wx : wy) : (lane < 24 ? wz : ww);
}

// shared-staged gather, MLP-8 unrolled
__device__ __forceinline__ void gather_unroll(const float* __restrict__ xw,
                                              const int* __restrict__ ssrc,
                                              const float (*sw)[4],
                                              int deg, int lane, int c, float4& acc) {
    int j = 0;
    for (; j + 8 <= deg; j += 8) {
        int   sj[8]; float wj[8]; float4 xv[8];
#pragma unroll
        for (int q = 0; q < 8; q++) { sj[q] = ssrc[j + q]; wj[q] = sw[j + q][c]; }
#pragma unroll
        for (int q = 0; q < 8; q++) xv[q] = *(const float4*)(xw + (size_t)sj[q] * HC + lane * 4);
#pragma unroll
        for (int q = 0; q < 8; q++) {
            acc.x += wj[q] * xv[q].x;
            acc.y += wj[q] * xv[q].y;
            acc.z += wj[q] * xv[q].z;
            acc.w += wj[q] * xv[q].w;
        }
    }
    for (; j + 4 <= deg; j += 4) {
        int   sj[4]; float wj[4]; float4 xv[4];
#pragma unroll
        for (int q = 0; q < 4; q++) { sj[q] = ssrc[j + q]; wj[q] = sw[j + q][c]; }
#pragma unroll
        for (int q = 0; q < 4; q++) xv[q] = *(const float4*)(xw + (size_t)sj[q] * HC + lane * 4);
#pragma unroll
        for (int q = 0; q < 4; q++) {
            acc.x += wj[q] * xv[q].x;
            acc.y += wj[q] * xv[q].y;
            acc.z += wj[q] * xv[q].z;
            acc.w += wj[q] * xv[q].w;
        }
    }
    for (; j < deg; j++) {
        int sj = ssrc[j];
        float wj = sw[j][c];
        float4 xr = *(const float4*)(xw + (size_t)sj * HC + lane * 4);
        acc.x += wj * xr.x;
        acc.y += wj * xr.y;
        acc.z += wj * xr.z;
        acc.w += wj * xr.w;
    }
}

// latency-bound kernel: force >=6 blocks/SM (48 warps) via reg cap
__global__ void __launch_bounds__(256, 6) k_agg(const float* __restrict__ xw,
                                                const float* __restrict__ sce,
                                                const float* __restrict__ bias,
                                                float* __restrict__ hout) {
    __shared__ int   s_src[8][32];
    __shared__ float s_w[8][32][4];
    int wid = threadIdx.x >> 5;
    int n = (blockIdx.x * 256 + threadIdx.x) >> 5;
    int lane = threadIdx.x & 31;
    if (n >= Nn) return;
    int s0 = g_rowptr[n], s1 = g_rowptr[n + 1];
    int deg = s1 - s0;
    float4 sd = *(const float4*)(g_scd + n * 4);
    float4 acc = make_float4(0.f, 0.f, 0.f, 0.f);

    if (deg <= 32) {
        int e = s0 + lane;
        bool v = e < s1;
        int srcv = 0;
        float4 raw = make_float4(-FLT_MAX, -FLT_MAX, -FLT_MAX, -FLT_MAX);
        if (v) {
            srcv = g_psrc[e];
            raw = raw_score(sce, srcv, e, sd);
        }
        float4 m = wmax4(raw);
        float4 a = make_float4(0.f, 0.f, 0.f, 0.f);
        if (v) {
            a.x = __expf(raw.x - m.x);
            a.y = __expf(raw.y - m.y);
            a.z = __expf(raw.z - m.z);
            a.w = __expf(raw.w - m.w);
        }
        float4 s = wsum4(a);
        s_src[wid][lane] = srcv;
        s_w[wid][lane][0] = a.x / (s.x + 1e-16f);
        s_w[wid][lane][1] = a.y / (s.y + 1e-16f);
        s_w[wid][lane][2] = a.z / (s.z + 1e-16f);
        s_w[wid][lane][3] = a.w / (s.w + 1e-16f);
        __syncwarp();
        gather_unroll(xw, s_src[wid], s_w[wid], deg, lane, lane >> 3, acc);
    } else {
        float4 pm = make_float4(-FLT_MAX, -FLT_MAX, -FLT_MAX, -FLT_MAX);
        for (int base = s0; base < s1; base += 32) {
            int e = base + lane;
            if (e < s1) {
                float4 raw = raw_score(sce, g_psrc[e], e, sd);
                pm.x = fmaxf(pm.x, raw.x); pm.y = fmaxf(pm.y, raw.y);
                pm.z = fmaxf(pm.z, raw.z); pm.w = fmaxf(pm.w, raw.w);
            }
        }
        float4 m = wmax4(pm);
        float4 ps = make_float4(0.f, 0.f, 0.f, 0.f);
        for (int base = s0; base < s1; base += 32) {
            int e = base + lane;
            if (e < s1) {
                float4 raw = raw_score(sce, g_psrc[e], e, sd);
                ps.x += __expf(raw.x - m.x);
                ps.y += __expf(raw.y - m.y);
                ps.z += __expf(raw.z - m.z);
                ps.w += __expf(raw.w - m.w);
            }
        }
        float4 s = wsum4(ps);
        float4 rinv;
        rinv.x = 1.f / (s.x + 1e-16f);
        rinv.y = 1.f / (s.y + 1e-16f);
        rinv.z = 1.f / (s.z + 1e-16f);
        rinv.w = 1.f / (s.w + 1e-16f);
        for (int base = s0; base < s1; base += 32) {
            int e = base + lane;
            int sv = 0;
            float4 wv = make_float4(0.f, 0.f, 0.f, 0.f);
            if (e < s1) {
                sv = g_psrc[e];
                float4 raw = raw_score(sce, sv, e, sd);
                wv.x = __expf(raw.x - m.x) * rinv.x;
                wv.y = __expf(raw.y - m.y) * rinv.y;
                wv.z = __expf(raw.z - m.z) * rinv.z;
                wv.w = __expf(raw.w - m.w) * rinv.w;
            }
            int c2 = s1 - base; if (c2 > 32) c2 = 32;
            for (int j = 0; j < c2; j++) {
                int sj = __shfl_sync(0xffffffffu, sv, j);
                float wsel = head_w(wv, j, lane);
                float4 xr = *(const float4*)(xw + (size_t)sj * HC + lane * 4);
                acc.x += wsel * xr.x;
                acc.y += wsel * xr.y;
                acc.z += wsel * xr.z;
                acc.w += wsel * xr.w;
            }
        }
    }
    float4 b4 = *(const float4*)(bias + lane * 4);
    float4 o4;
    o4.x = fmaxf(acc.x + b4.x, 0.f);
    o4.y = fmaxf(acc.y + b4.y, 0.f);
    o4.z = fmaxf(acc.z + b4.z, 0.f);
    o4.w = fmaxf(acc.w + b4.w, 0.f);
    *(float4*)(hout + (size_t)n * HC + lane * 4) = o4;
}

// ---------------- output head ----------------
__global__ void __launch_bounds__(128) k_pool(const float* __restrict__ h,
                                              const int* __restrict__ batch) {
    int t = threadIdx.x;
    int n0 = blockIdx.x * 64;
    int nend = n0 + 64; if (nend > Nn) nend = Nn;
    float acc = 0.f;
    int cnt = 0;
    int curb = batch[n0];
    for (int n = n0; n < nend; n++) {
        int b = batch[n];
        if (b != curb) {
            atomicAdd(&g_gsum[curb * HC + t], acc);
            if (t == 0) atomicAdd(&g_gcnt[curb], cnt);
            curb = b; acc = 0.f; cnt = 0;
        }
        acc += h[(size_t)n * HC + t];
        cnt++;
    }
    atomicAdd(&g_gsum[curb * HC + t], acc);
    if (t == 0) atomicAdd(&g_gcnt[curb], cnt);
}

__global__ void k_head(const float* __restrict__ Wl, const float* __restrict__ bl,
                       float* __restrict__ out) {
    int tid = threadIdx.x;
    if (tid >= Bb * Aa) return;
    int b = tid >> 3, a = tid & 7;
    float ic = 1.0f / fmaxf((float)g_gcnt[b], 1.0f);
    float s = 0.f;
    for (int c = 0; c < HC; c++) s += g_gsum[b * HC + c] * Wl[c * Aa + a];
    out[tid] = tanhf(s * ic + bl[a]);
}

// ---------------- launch ----------------
extern "C" void kernel_launch(void* const* d_in, const int* in_sizes, int n_in,
                              void* d_out, int out_size) {
    const float* slots[22];
    int k = 0;
    const int* ei = nullptr;
    const int* batch = nullptr;
    for (int i = 0; i < n_in; i++) {
        int sz = in_sizes[i];
        if (sz == 2 * Ee) ei = (const int*)d_in[i];
        else if (sz == Nn) batch = (const int*)d_in[i];
        else if (k < 22) slots[k++] = (const float*)d_in[i];
    }
    const float* x      = slots[0];
    const float* eattr  = slots[1];
    const float* W[3]   = { slots[2],  slots[8],  slots[14] };
    const float* We[3]  = { slots[3],  slots[9],  slots[15] };
    const float* aS[3]  = { slots[4],  slots[10], slots[16] };
    const float* aD[3]  = { slots[5],  slots[11], slots[17] };
    const float* aE[3]  = { slots[6],  slots[12], slots[18] };
    const float* bia[3] = { slots[7],  slots[13], slots[19] };
    const float* Wl = slots[20];
    const float* bl = slots[21];
    float* out = (float*)d_out;

    float *p_xw, *p_hA, *p_hB, *p_sce;
    cudaGetSymbolAddress((void**)&p_xw, g_xw);
    cudaGetSymbolAddress((void**)&p_hA, g_hA);
    cudaGetSymbolAddress((void**)&p_hB, g_hB);
    cudaGetSymbolAddress((void**)&p_sce, g_sce);

    k_init<<<(Nn + 255) / 256, 256>>>();
    k_count<<<(Ee + 255) / 256, 256>>>(ei);
    k_scan1<<<NB_SCAN, 256>>>();
    // launch #4 -> profiled by the fixed ncu window: track the GEMM
    k_gemm<64><<<(Nn + 31) / 32, 128>>>(x, W[0], aS[0], aD[0], p_xw);
    k_scan2<<<1, 256>>>();
    k_scan3<<<NB_SCAN, 256>>>();
    k_scatter<<<(Ee + 255) / 256, 256>>>(ei, eattr);
    k_meanattr<<<(Nn * 32 + 255) / 256, 256>>>();
    k_sce3<<<(EF + 255) / 256, 256>>>(We[0], aE[0], We[1], aE[1], We[2], aE[2]);

    const float* hin = x;
    float* houts[3] = { p_hA, p_hB, p_hA };
    for (int l = 0; l < 3; l++) {
        if (l > 0) k_gemm<128><<<(Nn + 31) / 32, 128>>>(hin, W[l], aS[l], aD[l], p_xw);
        k_agg<<<(Nn + 7) / 8, 256>>>(p_xw, p_sce + (size_t)l * EF * Hh, bia[l], houts[l]);
        hin = houts[l];
    }

    k_pool<<<(Nn + 63) / 64, 128>>>(hin, batch);
    k_head<<<1, 512>>>(Wl, bl, out);
}

// round 14
// speedup vs baseline: 1.0456x; 1.0061x over previous
#include <cuda_runtime.h>
#include <cstdint>
#include <cfloat>
#include <math.h>

#define Nn 50000
#define Ee 800000
#define EF 850000     // Ee + Nn self loops
#define FIN 64
#define EDIM 16
#define Hh 4
#define Cc 32
#define HC 128
#define Bb 64
#define Aa 8
#define NB_SCAN ((Nn + 255) / 256)   // 196

// ---------------- scratch ----------------
__device__ float g_xw[Nn * HC];
__device__ float g_hA[Nn * HC];
__device__ float g_hB[Nn * HC];
__device__ int   g_cnt[Nn];
__device__ int   g_fill[Nn];
__device__ int   g_rowptr[Nn + 1];
__device__ int   g_bsum[256];
__device__ int   g_boff[256];
__device__ int   g_psrc[EF];
__device__ float g_pattr[(size_t)EF * EDIM];     // CSR-permuted edge attrs (+ self-loop mean rows)
__device__ float g_sce[(size_t)3 * EF * Hh];     // per-layer edge scores
__device__ float g_scs[Nn * Hh];
__device__ float g_scd[Nn * Hh];
__device__ float g_gsum[Bb * HC];
__device__ int   g_gcnt[Bb];

// ---------------- helpers ----------------
__device__ __forceinline__ float lrelu(float v) { return v > 0.f ? v : 0.2f * v; }

__device__ __forceinline__ void cpa16(unsigned int saddr, const void* g, int sz) {
    asm volatile("cp.async.cg.shared.global [%0], [%1], 16, %2;\n"
                 :: "r"(saddr), "l"(g), "r"(sz) : "memory");
}

__device__ __forceinline__ float4 wmax4(float4 v) {
#pragma unroll
    for (int o = 16; o; o >>= 1) {
        v.x = fmaxf(v.x, __shfl_xor_sync(0xffffffffu, v.x, o));
        v.y = fmaxf(v.y, __shfl_xor_sync(0xffffffffu, v.y, o));
        v.z = fmaxf(v.z, __shfl_xor_sync(0xffffffffu, v.z, o));
        v.w = fmaxf(v.w, __shfl_xor_sync(0xffffffffu, v.w, o));
    }
    return v;
}
__device__ __forceinline__ float4 wsum4(float4 v) {
#pragma unroll
    for (int o = 16; o; o >>= 1) {
        v.x += __shfl_xor_sync(0xffffffffu, v.x, o);
        v.y += __shfl_xor_sync(0xffffffffu, v.y, o);
        v.z += __shfl_xor_sync(0xffffffffu, v.z, o);
        v.w += __shfl_xor_sync(0xffffffffu, v.w, o);
    }
    return v;
}

__device__ __forceinline__ float4 raw_score(const float* __restrict__ sce,
                                            int src, int e, float4 sd) {
    float4 ss = *(const float4*)(g_scs + src * 4);
    float4 se = *(const float4*)(sce + (size_t)e * 4);
    float4 r;
    r.x = lrelu(ss.x + sd.x + se.x);
    r.y = lrelu(ss.y + sd.y + se.y);
    r.z = lrelu(ss.z + sd.z + se.z);
    r.w = lrelu(ss.w + sd.w + se.w);
    return r;
}

// ---------------- preprocessing ----------------
__global__ void k_init() {
    int i = blockIdx.x * blockDim.x + threadIdx.x;
    if (i < Nn) { g_cnt[i] = 0; g_fill[i] = 0; }
    if (i < Bb * HC) g_gsum[i] = 0.f;
    if (i < Bb) g_gcnt[i] = 0;
}

__global__ void k_count(const int* __restrict__ ei) {
    int e = blockIdx.x * blockDim.x + threadIdx.x;
    if (e >= Ee) return;
    atomicAdd(&g_cnt[ei[Ee + e]], 1);
}

__global__ void k_scan1() {
    __shared__ int sh[256];
    int t = threadIdx.x;
    int i = blockIdx.x * 256 + t;
    int v = (i < Nn) ? (g_cnt[i] + 1) : 0;
    sh[t] = v;
    __syncthreads();
#pragma unroll
    for (int o = 1; o < 256; o <<= 1) {
        int u = (t >= o) ? sh[t - o] : 0;
        __syncthreads();
        sh[t] += u;
        __syncthreads();
    }
    if (i < Nn) g_rowptr[i] = sh[t] - v;
    if (t == 255) g_bsum[blockIdx.x] = sh[255];
}

__global__ void k_scan2() {
    __shared__ int sh[256];
    int t = threadIdx.x;
    int v = (t < NB_SCAN) ? g_bsum[t] : 0;
    sh[t] = v;
    __syncthreads();
#pragma unroll
    for (int o = 1; o < 256; o <<= 1) {
        int u = (t >= o) ? sh[t - o] : 0;
        __syncthreads();
        sh[t] += u;
        __syncthreads();
    }
    if (t < NB_SCAN) g_boff[t] = sh[t] - v;
    if (t == 255) g_rowptr[Nn] = sh[255];
}

__global__ void k_scan3() {
    int i = blockIdx.x * 256 + threadIdx.x;
    if (i < Nn) g_rowptr[i] += g_boff[blockIdx.x];
}

// scatter psrc + permute edge_attr into CSR order
__global__ void k_scatter(const int* __restrict__ ei, const float* __restrict__ eattr) {
    int e = blockIdx.x * blockDim.x + threadIdx.x;
    if (e >= Ee) return;
    int s = ei[e], d = ei[Ee + e];
    int pos = g_rowptr[d] + atomicAdd(&g_fill[d], 1);
    g_psrc[pos] = s;
    const float4* sp = (const float4*)(eattr + (size_t)e * EDIM);
    float4* dp = (float4*)(g_pattr + (size_t)pos * EDIM);
    dp[0] = sp[0]; dp[1] = sp[1]; dp[2] = sp[2]; dp[3] = sp[3];
}

// per-node mean of real in-edge attrs -> self-loop slot; psrc self = n
__global__ void __launch_bounds__(256) k_meanattr() {
    int n = (blockIdx.x * 256 + threadIdx.x) >> 5;
    int lane = threadIdx.x & 31;
    if (n >= Nn) return;
    int s0 = g_rowptr[n], s1 = g_rowptr[n + 1] - 1;   // real edges [s0,s1)
    float4 acc = make_float4(0.f, 0.f, 0.f, 0.f);
    const float4* pa = (const float4*)g_pattr;
    for (int r = s0 + (lane >> 2); r < s1; r += 8) {
        float4 v = pa[(size_t)r * 4 + (lane & 3)];
        acc.x += v.x; acc.y += v.y; acc.z += v.z; acc.w += v.w;
    }
#pragma unroll
    for (int o = 4; o < 32; o <<= 1) {
        acc.x += __shfl_xor_sync(0xffffffffu, acc.x, o);
        acc.y += __shfl_xor_sync(0xffffffffu, acc.y, o);
        acc.z += __shfl_xor_sync(0xffffffffu, acc.z, o);
        acc.w += __shfl_xor_sync(0xffffffffu, acc.w, o);
    }
    if (lane < 4) {
        float ic = 1.0f / fmaxf((float)(s1 - s0), 1.0f);
        acc.x *= ic; acc.y *= ic; acc.z *= ic; acc.w *= ic;
        ((float4*)g_pattr)[(size_t)s1 * 4 + lane] = acc;
    }
    if (lane == 0) g_psrc[s1] = n;
}

// ---------------- per-layer ----------------
// GEMM + fused score epilogue; 2-stage cp.async pipeline.
// 256 threads, M-tile 32: warp ty owns rows [4ty, 4ty+4), lane owns cols
// [4tx, 4tx+4). 4 rows/thread -> ~60 regs -> 4 blocks/SM = 32 warps (was 20).
template <int K>
__global__ void __launch_bounds__(256, 4) k_gemm(const float* __restrict__ A,
                                                 const float* __restrict__ W,
                                                 const float* __restrict__ a_s,
                                                 const float* __restrict__ a_d,
                                                 float* __restrict__ Out) {
    __shared__ float Ws[2][32][128];   // 32 KB
    __shared__ float Xs[2][32][32];    // 8 KB
    int tid = threadIdx.x;
    int tx = tid & 31, ty = tid >> 5;   // ty = 0..7
    int rowbase = blockIdx.x * 32;
    float4 acc[4];
#pragma unroll
    for (int r = 0; r < 4; r++) acc[r] = make_float4(0.f, 0.f, 0.f, 0.f);

    auto load_tiles = [&](int s, int kc) {
        // Ws: 32x128 = 1024 float4, 4 per thread
#pragma unroll
        for (int q = 0; q < 4; q++) {
            int idx = tid + 256 * q;
            int r = idx >> 5, c4 = idx & 31;
            cpa16((unsigned int)__cvta_generic_to_shared(&Ws[s][r][c4 * 4]),
                  &W[(size_t)(kc + r) * HC + c4 * 4], 16);
        }
        // Xs: 32x32 = 256 float4, 1 per thread
        {
            int r = tid >> 3, c4 = tid & 7;
            int row = rowbase + r;
            int ok = (row < Nn) ? 16 : 0;
            int rowc = (row < Nn) ? row : 0;
            cpa16((unsigned int)__cvta_generic_to_shared(&Xs[s][r][c4 * 4]),
                  &A[(size_t)rowc * K + kc + c4 * 4], ok);
        }
    };

    constexpr int NIT = K / 32;
    load_tiles(0, 0);
    asm volatile("cp.async.commit_group;" ::: "memory");

#pragma unroll
    for (int it = 0; it < NIT; it++) {
        int buf = it & 1;
        if (it + 1 < NIT) {
            load_tiles(buf ^ 1, (it + 1) * 32);
            asm volatile("cp.async.commit_group;" ::: "memory");
            asm volatile("cp.async.wait_group 1;" ::: "memory");
        } else {
            asm volatile("cp.async.wait_group 0;" ::: "memory");
        }
        __syncthreads();
#pragma unroll
        for (int k4 = 0; k4 < 32; k4 += 4) {
            float4 a4[4];
#pragma unroll
            for (int r = 0; r < 4; r++) a4[r] = *(const float4*)&Xs[buf][ty * 4 + r][k4];
#pragma unroll
            for (int kk = 0; kk < 4; kk++) {
                float4 b4 = *(const float4*)&Ws[buf][k4 + kk][tx * 4];
#pragma unroll
                for (int r = 0; r < 4; r++) {
                    float a = (kk == 0) ? a4[r].x : (kk == 1) ? a4[r].y : (kk == 2) ? a4[r].z : a4[r].w;
                    acc[r].x += a * b4.x;
                    acc[r].y += a * b4.y;
                    acc[r].z += a * b4.z;
                    acc[r].w += a * b4.w;
                }
            }
        }
        __syncthreads();
    }

    float4 as4 = *(const float4*)&a_s[tx * 4];
    float4 ad4 = *(const float4*)&a_d[tx * 4];
    int head = tx >> 3;

#pragma unroll
    for (int r = 0; r < 4; r++) {
        int row = rowbase + ty * 4 + r;
        if (row < Nn) {
            *(float4*)&Out[(size_t)row * HC + tx * 4] = acc[r];
            float ps = acc[r].x * as4.x + acc[r].y * as4.y + acc[r].z * as4.z + acc[r].w * as4.w;
            float pd = acc[r].x * ad4.x + acc[r].y * ad4.y + acc[r].z * ad4.z + acc[r].w * ad4.w;
#pragma unroll
            for (int o = 1; o < 8; o <<= 1) {
                ps += __shfl_xor_sync(0xffffffffu, ps, o);
                pd += __shfl_xor_sync(0xffffffffu, pd, o);
            }
            if ((tx & 7) == 0) {
                g_scs[row * 4 + head] = ps;
                g_scd[row * 4 + head] = pd;
            }
        }
    }
}

// ALL THREE layers' edge scores in one pass over pattr (read 54MB once, not 3x)
__global__ void k_sce3(const float* __restrict__ We0, const float* __restrict__ ae0,
                       const float* __restrict__ We1, const float* __restrict__ ae1,
                       const float* __restrict__ We2, const float* __restrict__ ae2) {
    __shared__ float ve[3][EDIM * Hh];
    int t = threadIdx.x;
    if (t < 3 * EDIM * Hh) {
        int l = t >> 6, u = t & 63;
        int d = u >> 2, h = u & 3;
        const float* We = (l == 0) ? We0 : (l == 1) ? We1 : We2;
        const float* ae = (l == 0) ? ae0 : (l == 1) ? ae1 : ae2;
        float s = 0.f;
#pragma unroll
        for (int c = 0; c < Cc; c++) s += We[d * HC + h * Cc + c] * ae[h * Cc + c];
        ve[l][u] = s;
    }
    __syncthreads();
    int i = blockIdx.x * blockDim.x + threadIdx.x;
    if (i >= EF) return;
    const float* ap = g_pattr + (size_t)i * EDIM;
    float4 av[4];
#pragma unroll
    for (int q = 0; q < 4; q++) av[q] = *(const float4*)(ap + q * 4);
#pragma unroll
    for (int l = 0; l < 3; l++) {
        const float* v = ve[l];
        float h0 = 0.f, h1 = 0.f, h2 = 0.f, h3 = 0.f;
#pragma unroll
        for (int q = 0; q < 4; q++) {
            int d = q * 4;
            h0 += av[q].x * v[d * 4 + 0] + av[q].y * v[(d + 1) * 4 + 0] + av[q].z * v[(d + 2) * 4 + 0] + av[q].w * v[(d + 3) * 4 + 0];
            h1 += av[q].x * v[d * 4 + 1] + av[q].y * v[(d + 1) * 4 + 1] + av[q].z * v[(d + 2) * 4 + 1] + av[q].w * v[(d + 3) * 4 + 1];
            h2 += av[q].x * v[d * 4 + 2] + av[q].y * v[(d + 1) * 4 + 2] + av[q].z * v[(d + 2) * 4 + 2] + av[q].w * v[(d + 3) * 4 + 2];
            h3 += av[q].x * v[d * 4 + 3] + av[q].y * v[(d + 1) * 4 + 3] + av[q].z * v[(d + 2) * 4 + 3] + av[q].w * v[(d + 3) * 4 + 3];
        }
        *(float4*)(g_sce + ((size_t)l * EF + i) * 4) = make_float4(h0, h1, h2, h3);
    }
}

// pick this lane's head weight from edge j's float4 weights (deg>32 fallback)
__device__ __forceinline__ float head_w(float4 wv, int j, int lane) {
    float wx = __shfl_sync(0xffffffffu, wv.x, j);
    float wy = __shfl_sync(0xffffffffu, wv.y, j);
    float wz = __shfl_sync(0xffffffffu, wv.z, j);
    float ww = __shfl_sync(0xffffffffu, wv.w, j);
    return lane < 16 ? (lane < 8 ? wx : wy) : (lane < 24 ? wz : ww);
}

// shared-staged gather, MLP-8 unrolled
__device__ __forceinline__ void gather_unroll(const float* __restrict__ xw,
                                              const int* __restrict__ ssrc,
                                              const float (*sw)[4],
                                              int deg, int lane, int c, float4& acc) {
    int j = 0;
    for (; j + 8 <= deg; j += 8) {
        int   sj[8]; float wj[8]; float4 xv[8];
#pragma unroll
        for (int q = 0; q < 8; q++) { sj[q] = ssrc[j + q]; wj[q] = sw[j + q][c]; }
#pragma unroll
        for (int q = 0; q < 8; q++) xv[q] = *(const float4*)(xw + (size_t)sj[q] * HC + lane * 4);
#pragma unroll
        for (int q = 0; q < 8; q++) {
            acc.x += wj[q] * xv[q].x;
            acc.y += wj[q] * xv[q].y;
            acc.z += wj[q] * xv[q].z;
            acc.w += wj[q] * xv[q].w;
        }
    }
    for (; j + 4 <= deg; j += 4) {
        int   sj[4]; float wj[4]; float4 xv[4];
#pragma unroll
        for (int q = 0; q < 4; q++) { sj[q] = ssrc[j + q]; wj[q] = sw[j + q][c]; }
#pragma unroll
        for (int q = 0; q < 4; q++) xv[q] = *(const float4*)(xw + (size_t)sj[q] * HC + lane * 4);
#pragma unroll
        for (int q = 0; q < 4; q++) {
            acc.x += wj[q] * xv[q].x;
            acc.y += wj[q] * xv[q].y;
            acc.z += wj[q] * xv[q].z;
            acc.w += wj[q] * xv[q].w;
        }
    }
    for (; j < deg; j++) {
        int sj = ssrc[j];
        float wj = sw[j][c];
        float4 xr = *(const float4*)(xw + (size_t)sj * HC + lane * 4);
        acc.x += wj * xr.x;
        acc.y += wj * xr.y;
        acc.z += wj * xr.z;
        acc.w += wj * xr.w;
    }
}

// latency-bound kernel: force >=6 blocks/SM (48 warps) via reg cap
__global__ void __launch_bounds__(256, 6) k_agg(const float* __restrict__ xw,
                                                const float* __restrict__ sce,
                                                const float* __restrict__ bias,
                                                float* __restrict__ hout) {
    __shared__ int   s_src[8][32];
    __shared__ float s_w[8][32][4];
    int wid = threadIdx.x >> 5;
    int n = (blockIdx.x * 256 + threadIdx.x) >> 5;
    int lane = threadIdx.x & 31;
    if (n >= Nn) return;
    int s0 = g_rowptr[n], s1 = g_rowptr[n + 1];
    int deg = s1 - s0;
    float4 sd = *(const float4*)(g_scd + n * 4);
    float4 acc = make_float4(0.f, 0.f, 0.f, 0.f);

    if (deg <= 32) {
        int e = s0 + lane;
        bool v = e < s1;
        int srcv = 0;
        float4 raw = make_float4(-FLT_MAX, -FLT_MAX, -FLT_MAX, -FLT_MAX);
        if (v) {
            srcv = g_psrc[e];
            raw = raw_score(sce, srcv, e, sd);
        }
        float4 m = wmax4(raw);
        float4 a = make_float4(0.f, 0.f, 0.f, 0.f);
        if (v) {
            a.x = __expf(raw.x - m.x);
            a.y = __expf(raw.y - m.y);
            a.z = __expf(raw.z - m.z);
            a.w = __expf(raw.w - m.w);
        }
        float4 s = wsum4(a);
        s_src[wid][lane] = srcv;
        s_w[wid][lane][0] = a.x / (s.x + 1e-16f);
        s_w[wid][lane][1] = a.y / (s.y + 1e-16f);
        s_w[wid][lane][2] = a.z / (s.z + 1e-16f);
        s_w[wid][lane][3] = a.w / (s.w + 1e-16f);
        __syncwarp();
        gather_unroll(xw, s_src[wid], s_w[wid], deg, lane, lane >> 3, acc);
    } else {
        float4 pm = make_float4(-FLT_MAX, -FLT_MAX, -FLT_MAX, -FLT_MAX);
        for (int base = s0; base < s1; base += 32) {
            int e = base + lane;
            if (e < s1) {
                float4 raw = raw_score(sce, g_psrc[e], e, sd);
                pm.x = fmaxf(pm.x, raw.x); pm.y = fmaxf(pm.y, raw.y);
                pm.z = fmaxf(pm.z, raw.z); pm.w = fmaxf(pm.w, raw.w);
            }
        }
        float4 m = wmax4(pm);
        float4 ps = make_float4(0.f, 0.f, 0.f, 0.f);
        for (int base = s0; base < s1; base += 32) {
            int e = base + lane;
            if (e < s1) {
                float4 raw = raw_score(sce, g_psrc[e], e, sd);
                ps.x += __expf(raw.x - m.x);
                ps.y += __expf(raw.y - m.y);
                ps.z += __expf(raw.z - m.z);
                ps.w += __expf(raw.w - m.w);
            }
        }
        float4 s = wsum4(ps);
        float4 rinv;
        rinv.x = 1.f / (s.x + 1e-16f);
        rinv.y = 1.f / (s.y + 1e-16f);
        rinv.z = 1.f / (s.z + 1e-16f);
        rinv.w = 1.f / (s.w + 1e-16f);
        for (int base = s0; base < s1; base += 32) {
            int e = base + lane;
            int sv = 0;
            float4 wv = make_float4(0.f, 0.f, 0.f, 0.f);
            if (e < s1) {
                sv = g_psrc[e];
                float4 raw = raw_score(sce, sv, e, sd);
                wv.x = __expf(raw.x - m.x) * rinv.x;
                wv.y = __expf(raw.y - m.y) * rinv.y;
                wv.z = __expf(raw.z - m.z) * rinv.z;
                wv.w = __expf(raw.w - m.w) * rinv.w;
            }
            int c2 = s1 - base; if (c2 > 32) c2 = 32;
            for (int j = 0; j < c2; j++) {
                int sj = __shfl_sync(0xffffffffu, sv, j);
                float wsel = head_w(wv, j, lane);
                float4 xr = *(const float4*)(xw + (size_t)sj * HC + lane * 4);
                acc.x += wsel * xr.x;
                acc.y += wsel * xr.y;
                acc.z += wsel * xr.z;
                acc.w += wsel * xr.w;
            }
        }
    }
    float4 b4 = *(const float4*)(bias + lane * 4);
    float4 o4;
    o4.x = fmaxf(acc.x + b4.x, 0.f);
    o4.y = fmaxf(acc.y + b4.y, 0.f);
    o4.z = fmaxf(acc.z + b4.z, 0.f);
    o4.w = fmaxf(acc.w + b4.w, 0.f);
    *(float4*)(hout + (size_t)n * HC + lane * 4) = o4;
}

// ---------------- output head ----------------
__global__ void __launch_bounds__(128) k_pool(const float* __restrict__ h,
                                              const int* __restrict__ batch) {
    int t = threadIdx.x;
    int n0 = blockIdx.x * 64;
    int nend = n0 + 64; if (nend > Nn) nend = Nn;
    float acc = 0.f;
    int cnt = 0;
    int curb = batch[n0];
    for (int n = n0; n < nend; n++) {
        int b = batch[n];
        if (b != curb) {
            atomicAdd(&g_gsum[curb * HC + t], acc);
            if (t == 0) atomicAdd(&g_gcnt[curb], cnt);
            curb = b; acc = 0.f; cnt = 0;
        }
        acc += h[(size_t)n * HC + t];
        cnt++;
    }
    atomicAdd(&g_gsum[curb * HC + t], acc);
    if (t == 0) atomicAdd(&g_gcnt[curb], cnt);
}

__global__ void k_head(const float* __restrict__ Wl, const float* __restrict__ bl,
                       float* __restrict__ out) {
    int tid = threadIdx.x;
    if (tid >= Bb * Aa) return;
    int b = tid >> 3, a = tid & 7;
    float ic = 1.0f / fmaxf((float)g_gcnt[b], 1.0f);
    float s = 0.f;
    for (int c = 0; c < HC; c++) s += g_gsum[b * HC + c] * Wl[c * Aa + a];
    out[tid] = tanhf(s * ic + bl[a]);
}

// ---------------- launch ----------------
extern "C" void kernel_launch(void* const* d_in, const int* in_sizes, int n_in,
                              void* d_out, int out_size) {
    const float* slots[22];
    int k = 0;
    const int* ei = nullptr;
    const int* batch = nullptr;
    for (int i = 0; i < n_in; i++) {
        int sz = in_sizes[i];
        if (sz == 2 * Ee) ei = (const int*)d_in[i];
        else if (sz == Nn) batch = (const int*)d_in[i];
        else if (k < 22) slots[k++] = (const float*)d_in[i];
    }
    const float* x      = slots[0];
    const float* eattr  = slots[1];
    const float* W[3]   = { slots[2],  slots[8],  slots[14] };
    const float* We[3]  = { slots[3],  slots[9],  slots[15] };
    const float* aS[3]  = { slots[4],  slots[10], slots[16] };
    const float* aD[3]  = { slots[5],  slots[11], slots[17] };
    const float* aE[3]  = { slots[6],  slots[12], slots[18] };
    const float* bia[3] = { slots[7],  slots[13], slots[19] };
    const float* Wl = slots[20];
    const float* bl = slots[21];
    float* out = (float*)d_out;

    float *p_xw, *p_hA, *p_hB, *p_sce;
    cudaGetSymbolAddress((void**)&p_xw, g_xw);
    cudaGetSymbolAddress((void**)&p_hA, g_hA);
    cudaGetSymbolAddress((void**)&p_hB, g_hB);
    cudaGetSymbolAddress((void**)&p_sce, g_sce);

    k_init<<<(Nn + 255) / 256, 256>>>();
    k_count<<<(Ee + 255) / 256, 256>>>(ei);
    k_scan1<<<NB_SCAN, 256>>>();
    // launch #4 -> profiled by the fixed ncu window: verify retiled GEMM occ/fma
    k_gemm<64><<<(Nn + 31) / 32, 256>>>(x, W[0], aS[0], aD[0], p_xw);
    k_scan2<<<1, 256>>>();
    k_scan3<<<NB_SCAN, 256>>>();
    k_scatter<<<(Ee + 255) / 256, 256>>>(ei, eattr);
    k_meanattr<<<(Nn * 32 + 255) / 256, 256>>>();
    k_sce3<<<(EF + 255) / 256, 256>>>(We[0], aE[0], We[1], aE[1], We[2], aE[2]);

    const float* hin = x;
    float* houts[3] = { p_hA, p_hB, p_hA };
    for (int l = 0; l < 3; l++) {
        if (l > 0) k_gemm<128><<<(Nn + 31) / 32, 256>>>(hin, W[l], aS[l], aD[l], p_xw);
        k_agg<<<(Nn + 7) / 8, 256>>>(p_xw, p_sce + (size_t)l * EF * Hh, bia[l], houts[l]);
        hin = houts[l];
    }

    k_pool<<<(Nn + 63) / 64, 128>>>(hin, batch);
    k_head<<<1, 512>>>(Wl, bl, out);
}

// round 16
// speedup vs baseline: 1.0484x; 1.0027x over previous
#include <cuda_runtime.h>
#include <cstdint>
#include <cfloat>
#include <math.h>

#define Nn 50000
#define Ee 800000
#define EF 850000     // Ee + Nn self loops
#define FIN 64
#define EDIM 16
#define Hh 4
#define Cc 32
#define HC 128
#define Bb 64
#define Aa 8
#define NB_SCAN ((Nn + 255) / 256)   // 196

// ---------------- scratch ----------------
__device__ float g_xw[Nn * HC];
__device__ float g_hA[Nn * HC];
__device__ float g_hB[Nn * HC];
__device__ int   g_cnt[Nn];
__device__ int   g_fill[Nn];
__device__ int   g_rowptr[Nn + 1];
__device__ int   g_bsum[256];
__device__ int   g_boff[256];
__device__ int   g_psrc[EF];
__device__ float g_pattr[(size_t)EF * EDIM];     // CSR-permuted edge attrs (+ self-loop mean rows)
__device__ float g_sce[(size_t)3 * EF * Hh];     // per-layer edge scores
__device__ float g_scs[Nn * Hh];
__device__ float g_scd[Nn * Hh];
__device__ float g_gsum[Bb * HC];
__device__ int   g_gcnt[Bb];

// ---------------- helpers ----------------
__device__ __forceinline__ float lrelu(float v) { return v > 0.f ? v : 0.2f * v; }

__device__ __forceinline__ void cpa16(unsigned int saddr, const void* g, int sz) {
    asm volatile("cp.async.cg.shared.global [%0], [%1], 16, %2;\n"
                 :: "r"(saddr), "l"(g), "r"(sz) : "memory");
}

__device__ __forceinline__ float4 wmax4(float4 v) {
#pragma unroll
    for (int o = 16; o; o >>= 1) {
        v.x = fmaxf(v.x, __shfl_xor_sync(0xffffffffu, v.x, o));
        v.y = fmaxf(v.y, __shfl_xor_sync(0xffffffffu, v.y, o));
        v.z = fmaxf(v.z, __shfl_xor_sync(0xffffffffu, v.z, o));
        v.w = fmaxf(v.w, __shfl_xor_sync(0xffffffffu, v.w, o));
    }
    return v;
}
__device__ __forceinline__ float4 wsum4(float4 v) {
#pragma unroll
    for (int o = 16; o; o >>= 1) {
        v.x += __shfl_xor_sync(0xffffffffu, v.x, o);
        v.y += __shfl_xor_sync(0xffffffffu, v.y, o);
        v.z += __shfl_xor_sync(0xffffffffu, v.z, o);
        v.w += __shfl_xor_sync(0xffffffffu, v.w, o);
    }
    return v;
}

__device__ __forceinline__ float4 raw_score(const float* __restrict__ sce,
                                            int src, int e, float4 sd) {
    float4 ss = *(const float4*)(g_scs + src * 4);
    float4 se = *(const float4*)(sce + (size_t)e * 4);
    float4 r;
    r.x = lrelu(ss.x + sd.x + se.x);
    r.y = lrelu(ss.y + sd.y + se.y);
    r.z = lrelu(ss.z + sd.z + se.z);
    r.w = lrelu(ss.w + sd.w + se.w);
    return r;
}

// ---------------- preprocessing ----------------
__global__ void k_init() {
    int i = blockIdx.x * blockDim.x + threadIdx.x;
    if (i < Nn) { g_cnt[i] = 0; g_fill[i] = 0; }
    if (i < Bb * HC) g_gsum[i] = 0.f;
    if (i < Bb) g_gcnt[i] = 0;
}

__global__ void k_count(const int* __restrict__ ei) {
    int e = blockIdx.x * blockDim.x + threadIdx.x;
    if (e >= Ee) return;
    atomicAdd(&g_cnt[ei[Ee + e]], 1);
}

__global__ void k_scan1() {
    __shared__ int sh[256];
    int t = threadIdx.x;
    int i = blockIdx.x * 256 + t;
    int v = (i < Nn) ? (g_cnt[i] + 1) : 0;
    sh[t] = v;
    __syncthreads();
#pragma unroll
    for (int o = 1; o < 256; o <<= 1) {
        int u = (t >= o) ? sh[t - o] : 0;
        __syncthreads();
        sh[t] += u;
        __syncthreads();
    }
    if (i < Nn) g_rowptr[i] = sh[t] - v;
    if (t == 255) g_bsum[blockIdx.x] = sh[255];
}

__global__ void k_scan2() {
    __shared__ int sh[256];
    int t = threadIdx.x;
    int v = (t < NB_SCAN) ? g_bsum[t] : 0;
    sh[t] = v;
    __syncthreads();
#pragma unroll
    for (int o = 1; o < 256; o <<= 1) {
        int u = (t >= o) ? sh[t - o] : 0;
        __syncthreads();
        sh[t] += u;
        __syncthreads();
    }
    if (t < NB_SCAN) g_boff[t] = sh[t] - v;
    if (t == 255) g_rowptr[Nn] = sh[255];
}

__global__ void k_scan3() {
    int i = blockIdx.x * 256 + threadIdx.x;
    if (i < Nn) g_rowptr[i] += g_boff[blockIdx.x];
}

// scatter psrc + permute edge_attr into CSR order
__global__ void k_scatter(const int* __restrict__ ei, const float* __restrict__ eattr) {
    int e = blockIdx.x * blockDim.x + threadIdx.x;
    if (e >= Ee) return;
    int s = ei[e], d = ei[Ee + e];
    int pos = g_rowptr[d] + atomicAdd(&g_fill[d], 1);
    g_psrc[pos] = s;
    const float4* sp = (const float4*)(eattr + (size_t)e * EDIM);
    float4* dp = (float4*)(g_pattr + (size_t)pos * EDIM);
    dp[0] = sp[0]; dp[1] = sp[1]; dp[2] = sp[2]; dp[3] = sp[3];
}

// per-node mean of real in-edge attrs -> self-loop slot; psrc self = n
__global__ void __launch_bounds__(256) k_meanattr() {
    int n = (blockIdx.x * 256 + threadIdx.x) >> 5;
    int lane = threadIdx.x & 31;
    if (n >= Nn) return;
    int s0 = g_rowptr[n], s1 = g_rowptr[n + 1] - 1;   // real edges [s0,s1)
    float4 acc = make_float4(0.f, 0.f, 0.f, 0.f);
    const float4* pa = (const float4*)g_pattr;
    for (int r = s0 + (lane >> 2); r < s1; r += 8) {
        float4 v = pa[(size_t)r * 4 + (lane & 3)];
        acc.x += v.x; acc.y += v.y; acc.z += v.z; acc.w += v.w;
    }
#pragma unroll
    for (int o = 4; o < 32; o <<= 1) {
        acc.x += __shfl_xor_sync(0xffffffffu, acc.x, o);
        acc.y += __shfl_xor_sync(0xffffffffu, acc.y, o);
        acc.z += __shfl_xor_sync(0xffffffffu, acc.z, o);
        acc.w += __shfl_xor_sync(0xffffffffu, acc.w, o);
    }
    if (lane < 4) {
        float ic = 1.0f / fmaxf((float)(s1 - s0), 1.0f);
        acc.x *= ic; acc.y *= ic; acc.z *= ic; acc.w *= ic;
        ((float4*)g_pattr)[(size_t)s1 * 4 + lane] = acc;
    }
    if (lane == 0) g_psrc[s1] = n;
}

// ---------------- per-layer ----------------
// GEMM + fused score epilogue; 2-stage cp.async pipeline.
// 256 threads, M-tile 64: warp ty owns rows [8ty, 8ty+8), lane owns 4 cols.
// 128 FFMA per 12 LDS-inst per 4 k-steps; 3 blocks/SM = 24 warps.
template <int K>
__global__ void __launch_bounds__(256, 3) k_gemm(const float* __restrict__ A,
                                                 const float* __restrict__ W,
                                                 const float* __restrict__ a_s,
                                                 const float* __restrict__ a_d,
                                                 float* __restrict__ Out) {
    __shared__ float Ws[2][32][128];   // 32 KB
    __shared__ float Xs[2][64][32];    // 16 KB
    int tid = threadIdx.x;
    int tx = tid & 31, ty = tid >> 5;   // ty = 0..7
    int rowbase = blockIdx.x * 64;
    float4 acc[8];
#pragma unroll
    for (int r = 0; r < 8; r++) acc[r] = make_float4(0.f, 0.f, 0.f, 0.f);

    auto load_tiles = [&](int s, int kc) {
        // Ws: 32x128 = 1024 float4, 4 per thread
#pragma unroll
        for (int q = 0; q < 4; q++) {
            int idx = tid + 256 * q;
            int r = idx >> 5, c4 = idx & 31;
            cpa16((unsigned int)__cvta_generic_to_shared(&Ws[s][r][c4 * 4]),
                  &W[(size_t)(kc + r) * HC + c4 * 4], 16);
        }
        // Xs: 64x32 = 512 float4, 2 per thread
#pragma unroll
        for (int q = 0; q < 2; q++) {
            int idx = tid + 256 * q;
            int r = idx >> 3, c4 = idx & 7;
            int row = rowbase + r;
            int ok = (row < Nn) ? 16 : 0;
            int rowc = (row < Nn) ? row : 0;
            cpa16((unsigned int)__cvta_generic_to_shared(&Xs[s][r][c4 * 4]),
                  &A[(size_t)rowc * K + kc + c4 * 4], ok);
        }
    };

    constexpr int NIT = K / 32;
    load_tiles(0, 0);
    asm volatile("cp.async.commit_group;" ::: "memory");

#pragma unroll
    for (int it = 0; it < NIT; it++) {
        int buf = it & 1;
        if (it + 1 < NIT) {
            load_tiles(buf ^ 1, (it + 1) * 32);
            asm volatile("cp.async.commit_group;" ::: "memory");
            asm volatile("cp.async.wait_group 1;" ::: "memory");
        } else {
            asm volatile("cp.async.wait_group 0;" ::: "memory");
        }
        __syncthreads();
#pragma unroll
        for (int k4 = 0; k4 < 32; k4 += 4) {
            float4 a4[8];
#pragma unroll
            for (int r = 0; r < 8; r++) a4[r] = *(const float4*)&Xs[buf][ty * 8 + r][k4];
#pragma unroll
            for (int kk = 0; kk < 4; kk++) {
                float4 b4 = *(const float4*)&Ws[buf][k4 + kk][tx * 4];
#pragma unroll
                for (int r = 0; r < 8; r++) {
                    float a = (kk == 0) ? a4[r].x : (kk == 1) ? a4[r].y : (kk == 2) ? a4[r].z : a4[r].w;
                    acc[r].x += a * b4.x;
                    acc[r].y += a * b4.y;
                    acc[r].z += a * b4.z;
                    acc[r].w += a * b4.w;
                }
            }
        }
        __syncthreads();
    }

    float4 as4 = *(const float4*)&a_s[tx * 4];
    float4 ad4 = *(const float4*)&a_d[tx * 4];
    int head = tx >> 3;

#pragma unroll
    for (int r = 0; r < 8; r++) {
        int row = rowbase + ty * 8 + r;
        if (row < Nn) {
            *(float4*)&Out[(size_t)row * HC + tx * 4] = acc[r];
            float ps = acc[r].x * as4.x + acc[r].y * as4.y + acc[r].z * as4.z + acc[r].w * as4.w;
            float pd = acc[r].x * ad4.x + acc[r].y * ad4.y + acc[r].z * ad4.z + acc[r].w * ad4.w;
#pragma unroll
            for (int o = 1; o < 8; o <<= 1) {
                ps += __shfl_xor_sync(0xffffffffu, ps, o);
                pd += __shfl_xor_sync(0xffffffffu, pd, o);
            }
            if ((tx & 7) == 0) {
                g_scs[row * 4 + head] = ps;
                g_scd[row * 4 + head] = pd;
            }
        }
    }
}

// ALL THREE layers' edge scores in one pass over pattr (read 54MB once, not 3x)
__global__ void k_sce3(const float* __restrict__ We0, const float* __restrict__ ae0,
                       const float* __restrict__ We1, const float* __restrict__ ae1,
                       const float* __restrict__ We2, const float* __restrict__ ae2) {
    __shared__ float ve[3][EDIM * Hh];
    int t = threadIdx.x;
    if (t < 3 * EDIM * Hh) {
        int l = t >> 6, u = t & 63;
        int d = u >> 2, h = u & 3;
        const float* We = (l == 0) ? We0 : (l == 1) ? We1 : We2;
        const float* ae = (l == 0) ? ae0 : (l == 1) ? ae1 : ae2;
        float s = 0.f;
#pragma unroll
        for (int c = 0; c < Cc; c++) s += We[d * HC + h * Cc + c] * ae[h * Cc + c];
        ve[l][u] = s;
    }
    __syncthreads();
    int i = blockIdx.x * blockDim.x + threadIdx.x;
    if (i >= EF) return;
    const float* ap = g_pattr + (size_t)i * EDIM;
    float4 av[4];
#pragma unroll
    for (int q = 0; q < 4; q++) av[q] = *(const float4*)(ap + q * 4);
#pragma unroll
    for (int l = 0; l < 3; l++) {
        const float* v = ve[l];
        float h0 = 0.f, h1 = 0.f, h2 = 0.f, h3 = 0.f;
#pragma unroll
        for (int q = 0; q < 4; q++) {
            int d = q * 4;
            h0 += av[q].x * v[d * 4 + 0] + av[q].y * v[(d + 1) * 4 + 0] + av[q].z * v[(d + 2) * 4 + 0] + av[q].w * v[(d + 3) * 4 + 0];
            h1 += av[q].x * v[d * 4 + 1] + av[q].y * v[(d + 1) * 4 + 1] + av[q].z * v[(d + 2) * 4 + 1] + av[q].w * v[(d + 3) * 4 + 1];
            h2 += av[q].x * v[d * 4 + 2] + av[q].y * v[(d + 1) * 4 + 2] + av[q].z * v[(d + 2) * 4 + 2] + av[q].w * v[(d + 3) * 4 + 2];
            h3 += av[q].x * v[d * 4 + 3] + av[q].y * v[(d + 1) * 4 + 3] + av[q].z * v[(d + 2) * 4 + 3] + av[q].w * v[(d + 3) * 4 + 3];
        }
        *(float4*)(g_sce + ((size_t)l * EF + i) * 4) = make_float4(h0, h1, h2, h3);
    }
}

// pick this lane's head weight from edge j's float4 weights (deg>32 fallback)
__device__ __forceinline__ float head_w(float4 wv, int j, int lane) {
    float wx = __shfl_sync(0xffffffffu, wv.x, j);
    float wy = __shfl_sync(0xffffffffu, wv.y, j);
    float wz = __shfl_sync(0xffffffffu, wv.z, j);
    float ww = __shfl_sync(0xffffffffu, wv.w, j);
    return lane < 16 ? (lane < 8 ? wx : wy) : (lane < 24 ? wz : ww);
}

// shared-staged gather, MLP-8 unrolled
__device__ __forceinline__ void gather_unroll(const float* __restrict__ xw,
                                              const int* __restrict__ ssrc,
                                              const float (*sw)[4],
                                              int deg, int lane, int c, float4& acc) {
    int j = 0;
    for (; j + 8 <= deg; j += 8) {
        int   sj[8]; float wj[8]; float4 xv[8];
#pragma unroll
        for (int q = 0; q < 8; q++) { sj[q] = ssrc[j + q]; wj[q] = sw[j + q][c]; }
#pragma unroll
        for (int q = 0; q < 8; q++) xv[q] = *(const float4*)(xw + (size_t)sj[q] * HC + lane * 4);
#pragma unroll
        for (int q = 0; q < 8; q++) {
            acc.x += wj[q] * xv[q].x;
            acc.y += wj[q] * xv[q].y;
            acc.z += wj[q] * xv[q].z;
            acc.w += wj[q] * xv[q].w;
        }
    }
    for (; j + 4 <= deg; j += 4) {
        int   sj[4]; float wj[4]; float4 xv[4];
#pragma unroll
        for (int q = 0; q < 4; q++) { sj[q] = ssrc[j + q]; wj[q] = sw[j + q][c]; }
#pragma unroll
        for (int q = 0; q < 4; q++) xv[q] = *(const float4*)(xw + (size_t)sj[q] * HC + lane * 4);
#pragma unroll
        for (int q = 0; q < 4; q++) {
            acc.x += wj[q] * xv[q].x;
            acc.y += wj[q] * xv[q].y;
            acc.z += wj[q] * xv[q].z;
            acc.w += wj[q] * xv[q].w;
        }
    }
    for (; j < deg; j++) {
        int sj = ssrc[j];
        float wj = sw[j][c];
        float4 xr = *(const float4*)(xw + (size_t)sj * HC + lane * 4);
        acc.x += wj * xr.x;
        acc.y += wj * xr.y;
        acc.z += wj * xr.z;
        acc.w += wj * xr.w;
    }
}

// latency-bound kernel: force >=6 blocks/SM (48 warps) via reg cap
__global__ void __launch_bounds__(256, 6) k_agg(const float* __restrict__ xw,
                                                const float* __restrict__ sce,
                                                const float* __restrict__ bias,
                                                float* __restrict__ hout) {
    __shared__ int   s_src[8][32];
    __shared__ float s_w[8][32][4];
    int wid = threadIdx.x >> 5;
    int n = (blockIdx.x * 256 + threadIdx.x) >> 5;
    int lane = threadIdx.x & 31;
    if (n >= Nn) return;
    int s0 = g_rowptr[n], s1 = g_rowptr[n + 1];
    int deg = s1 - s0;
    float4 sd = *(const float4*)(g_scd + n * 4);
    float4 acc = make_float4(0.f, 0.f, 0.f, 0.f);

    if (deg <= 32) {
        int e = s0 + lane;
        bool v = e < s1;
        int srcv = 0;
        float4 raw = make_float4(-FLT_MAX, -FLT_MAX, -FLT_MAX, -FLT_MAX);
        if (v) {
            srcv = g_psrc[e];
            raw = raw_score(sce, srcv, e, sd);
        }
        float4 m = wmax4(raw);
        float4 a = make_float4(0.f, 0.f, 0.f, 0.f);
        if (v) {
            a.x = __expf(raw.x - m.x);
            a.y = __expf(raw.y - m.y);
            a.z = __expf(raw.z - m.z);
            a.w = __expf(raw.w - m.w);
        }
        float4 s = wsum4(a);
        s_src[wid][lane] = srcv;
        s_w[wid][lane][0] = a.x / (s.x + 1e-16f);
        s_w[wid][lane][1] = a.y / (s.y + 1e-16f);
        s_w[wid][lane][2] = a.z / (s.z + 1e-16f);
        s_w[wid][lane][3] = a.w / (s.w + 1e-16f);
        __syncwarp();
        gather_unroll(xw, s_src[wid], s_w[wid], deg, lane, lane >> 3, acc);
    } else {
        float4 pm = make_float4(-FLT_MAX, -FLT_MAX, -FLT_MAX, -FLT_MAX);
        for (int base = s0; base < s1; base += 32) {
            int e = base + lane;
            if (e < s1) {
                float4 raw = raw_score(sce, g_psrc[e], e, sd);
                pm.x = fmaxf(pm.x, raw.x); pm.y = fmaxf(pm.y, raw.y);
                pm.z = fmaxf(pm.z, raw.z); pm.w = fmaxf(pm.w, raw.w);
            }
        }
        float4 m = wmax4(pm);
        float4 ps = make_float4(0.f, 0.f, 0.f, 0.f);
        for (int base = s0; base < s1; base += 32) {
            int e = base + lane;
            if (e < s1) {
                float4 raw = raw_score(sce, g_psrc[e], e, sd);
                ps.x += __expf(raw.x - m.x);
                ps.y += __expf(raw.y - m.y);
                ps.z += __expf(raw.z - m.z);
                ps.w += __expf(raw.w - m.w);
            }
        }
        float4 s = wsum4(ps);
        float4 rinv;
        rinv.x = 1.f / (s.x + 1e-16f);
        rinv.y = 1.f / (s.y + 1e-16f);
        rinv.z = 1.f / (s.z + 1e-16f);
        rinv.w = 1.f / (s.w + 1e-16f);
        for (int base = s0; base < s1; base += 32) {
            int e = base + lane;
            int sv = 0;
            float4 wv = make_float4(0.f, 0.f, 0.f, 0.f);
            if (e < s1) {
                sv = g_psrc[e];
                float4 raw = raw_score(sce, sv, e, sd);
                wv.x = __expf(raw.x - m.x) * rinv.x;
                wv.y = __expf(raw.y - m.y) * rinv.y;
                wv.z = __expf(raw.z - m.z) * rinv.z;
                wv.w = __expf(raw.w - m.w) * rinv.w;
            }
            int c2 = s1 - base; if (c2 > 32) c2 = 32;
            for (int j = 0; j < c2; j++) {
                int sj = __shfl_sync(0xffffffffu, sv, j);
                float wsel = head_w(wv, j, lane);
                float4 xr = *(const float4*)(xw + (size_t)sj * HC + lane * 4);
                acc.x += wsel * xr.x;
                acc.y += wsel * xr.y;
                acc.z += wsel * xr.z;
                acc.w += wsel * xr.w;
            }
        }
    }
    float4 b4 = *(const float4*)(bias + lane * 4);
    float4 o4;
    o4.x = fmaxf(acc.x + b4.x, 0.f);
    o4.y = fmaxf(acc.y + b4.y, 0.f);
    o4.z = fmaxf(acc.z + b4.z, 0.f);
    o4.w = fmaxf(acc.w + b4.w, 0.f);
    *(float4*)(hout + (size_t)n * HC + lane * 4) = o4;
}

// ---------------- output head ----------------
__global__ void __launch_bounds__(128) k_pool(const float* __restrict__ h,
                                              const int* __restrict__ batch) {
    int t = threadIdx.x;
    int n0 = blockIdx.x * 64;
    int nend = n0 + 64; if (nend > Nn) nend = Nn;
    float acc = 0.f;
    int cnt = 0;
    int curb = batch[n0];
    for (int n = n0; n < nend; n++) {
        int b = batch[n];
        if (b != curb) {
            atomicAdd(&g_gsum[curb * HC + t], acc);
            if (t == 0) atomicAdd(&g_gcnt[curb], cnt);
            curb = b; acc = 0.f; cnt = 0;
        }
        acc += h[(size_t)n * HC + t];
        cnt++;
    }
    atomicAdd(&g_gsum[curb * HC + t], acc);
    if (t == 0) atomicAdd(&g_gcnt[curb], cnt);
}

__global__ void k_head(const float* __restrict__ Wl, const float* __restrict__ bl,
                       float* __restrict__ out) {
    int tid = threadIdx.x;
    if (tid >= Bb * Aa) return;
    int b = tid >> 3, a = tid & 7;
    float ic = 1.0f / fmaxf((float)g_gcnt[b], 1.0f);
    float s = 0.f;
    for (int c = 0; c < HC; c++) s += g_gsum[b * HC + c] * Wl[c * Aa + a];
    out[tid] = tanhf(s * ic + bl[a]);
}

// ---------------- launch ----------------
extern "C" void kernel_launch(void* const* d_in, const int* in_sizes, int n_in,
                              void* d_out, int out_size) {
    const float* slots[22];
    int k = 0;
    const int* ei = nullptr;
    const int* batch = nullptr;
    for (int i = 0; i < n_in; i++) {
        int sz = in_sizes[i];
        if (sz == 2 * Ee) ei = (const int*)d_in[i];
        else if (sz == Nn) batch = (const int*)d_in[i];
        else if (k < 22) slots[k++] = (const float*)d_in[i];
    }
    const float* x      = slots[0];
    const float* eattr  = slots[1];
    const float* W[3]   = { slots[2],  slots[8],  slots[14] };
    const float* We[3]  = { slots[3],  slots[9],  slots[15] };
    const float* aS[3]  = { slots[4],  slots[10], slots[16] };
    const float* aD[3]  = { slots[5],  slots[11], slots[17] };
    const float* aE[3]  = { slots[6],  slots[12], slots[18] };
    const float* bia[3] = { slots[7],  slots[13], slots[19] };
    const float* Wl = slots[20];
    const float* bl = slots[21];
    float* out = (float*)d_out;

    float *p_xw, *p_hA, *p_hB, *p_sce;
    cudaGetSymbolAddress((void**)&p_xw, g_xw);
    cudaGetSymbolAddress((void**)&p_hA, g_hA);
    cudaGetSymbolAddress((void**)&p_hB, g_hB);
    cudaGetSymbolAddress((void**)&p_sce, g_sce);

    k_init<<<(Nn + 255) / 256, 256>>>();
    k_count<<<(Ee + 255) / 256, 256>>>(ei);
    k_scan1<<<NB_SCAN, 256>>>();
    // launch #4 -> profiled by the fixed ncu window: verify M64 retile occ/fma/L1
    k_gemm<64><<<(Nn + 63) / 64, 256>>>(x, W[0], aS[0], aD[0], p_xw);
    k_scan2<<<1, 256>>>();
    k_scan3<<<NB_SCAN, 256>>>();
    k_scatter<<<(Ee + 255) / 256, 256>>>(ei, eattr);
    k_meanattr<<<(Nn * 32 + 255) / 256, 256>>>();
    k_sce3<<<(EF + 255) / 256, 256>>>(We[0], aE[0], We[1], aE[1], We[2], aE[2]);

    const float* hin = x;
    float* houts[3] = { p_hA, p_hB, p_hA };
    for (int l = 0; l < 3; l++) {
        if (l > 0) k_gemm<128><<<(Nn + 63) / 64, 256>>>(hin, W[l], aS[l], aD[l], p_xw);
        k_agg<<<(Nn + 7) / 8, 256>>>(p_xw, p_sce + (size_t)l * EF * Hh, bia[l], houts[l]);
        hin = houts[l];
    }

    k_pool<<<(Nn + 63) / 64, 128>>>(hin, batch);
    k_head<<<1, 512>>>(Wl, bl, out);
}

// round 17
// speedup vs baseline: 1.0671x; 1.0179x over previous
#include <cuda_runtime.h>
#include <cuda_fp16.h>
#include <cstdint>
#include <cfloat>
#include <math.h>

#define Nn 50000
#define Ee 800000
#define EF 850000     // Ee + Nn self loops
#define FIN 64
#define EDIM 16
#define Hh 4
#define Cc 32
#define HC 128
#define Bb 64
#define Aa 8
#define NB_SCAN ((Nn + 255) / 256)   // 196

// ---------------- scratch ----------------
__device__ __half g_xwh[Nn * HC];               // fp16 xw: gather-only consumer
__device__ float g_hA[Nn * HC];
__device__ float g_hB[Nn * HC];
__device__ int   g_cnt[Nn];
__device__ int   g_fill[Nn];
__device__ int   g_rowptr[Nn + 1];
__device__ int   g_bsum[256];
__device__ int   g_boff[256];
__device__ int   g_psrc[EF];
__device__ float g_pattr[(size_t)EF * EDIM];     // CSR-permuted edge attrs (+ self-loop mean rows)
__device__ float g_sce[(size_t)3 * EF * Hh];     // per-layer edge scores
__device__ float g_scs[Nn * Hh];
__device__ float g_scd[Nn * Hh];
__device__ float g_gsum[Bb * HC];
__device__ int   g_gcnt[Bb];

// ---------------- helpers ----------------
__device__ __forceinline__ float lrelu(float v) { return v > 0.f ? v : 0.2f * v; }

__device__ __forceinline__ void cpa16(unsigned int saddr, const void* g, int sz) {
    asm volatile("cp.async.cg.shared.global [%0], [%1], 16, %2;\n"
                 :: "r"(saddr), "l"(g), "r"(sz) : "memory");
}

__device__ __forceinline__ float4 half4_load(const __half* p) {
    uint2 u = *(const uint2*)p;
    __half2 h01 = *reinterpret_cast<__half2*>(&u.x);
    __half2 h23 = *reinterpret_cast<__half2*>(&u.y);
    float2 f01 = __half22float2(h01);
    float2 f23 = __half22float2(h23);
    return make_float4(f01.x, f01.y, f23.x, f23.y);
}

__device__ __forceinline__ float4 wmax4(float4 v) {
#pragma unroll
    for (int o = 16; o; o >>= 1) {
        v.x = fmaxf(v.x, __shfl_xor_sync(0xffffffffu, v.x, o));
        v.y = fmaxf(v.y, __shfl_xor_sync(0xffffffffu, v.y, o));
        v.z = fmaxf(v.z, __shfl_xor_sync(0xffffffffu, v.z, o));
        v.w = fmaxf(v.w, __shfl_xor_sync(0xffffffffu, v.w, o));
    }
    return v;
}
__device__ __forceinline__ float4 wsum4(float4 v) {
#pragma unroll
    for (int o = 16; o; o >>= 1) {
        v.x += __shfl_xor_sync(0xffffffffu, v.x, o);
        v.y += __shfl_xor_sync(0xffffffffu, v.y, o);
        v.z += __shfl_xor_sync(0xffffffffu, v.z, o);
        v.w += __shfl_xor_sync(0xffffffffu, v.w, o);
    }
    return v;
}

__device__ __forceinline__ float4 raw_score(const float* __restrict__ sce,
                                            int src, int e, float4 sd) {
    float4 ss = *(const float4*)(g_scs + src * 4);
    float4 se = *(const float4*)(sce + (size_t)e * 4);
    float4 r;
    r.x = lrelu(ss.x + sd.x + se.x);
    r.y = lrelu(ss.y + sd.y + se.y);
    r.z = lrelu(ss.z + sd.z + se.z);
    r.w = lrelu(ss.w + sd.w + se.w);
    return r;
}

// ---------------- preprocessing ----------------
__global__ void k_init() {
    int i = blockIdx.x * blockDim.x + threadIdx.x;
    if (i < Nn) { g_cnt[i] = 0; g_fill[i] = 0; }
    if (i < Bb * HC) g_gsum[i] = 0.f;
    if (i < Bb) g_gcnt[i] = 0;
}

__global__ void k_count(const int* __restrict__ ei) {
    int e = blockIdx.x * blockDim.x + threadIdx.x;
    if (e >= Ee) return;
    atomicAdd(&g_cnt[ei[Ee + e]], 1);
}

__global__ void k_scan1() {
    __shared__ int sh[256];
    int t = threadIdx.x;
    int i = blockIdx.x * 256 + t;
    int v = (i < Nn) ? (g_cnt[i] + 1) : 0;
    sh[t] = v;
    __syncthreads();
#pragma unroll
    for (int o = 1; o < 256; o <<= 1) {
        int u = (t >= o) ? sh[t - o] : 0;
        __syncthreads();
        sh[t] += u;
        __syncthreads();
    }
    if (i < Nn) g_rowptr[i] = sh[t] - v;
    if (t == 255) g_bsum[blockIdx.x] = sh[255];
}

__global__ void k_scan2() {
    __shared__ int sh[256];
    int t = threadIdx.x;
    int v = (t < NB_SCAN) ? g_bsum[t] : 0;
    sh[t] = v;
    __syncthreads();
#pragma unroll
    for (int o = 1; o < 256; o <<= 1) {
        int u = (t >= o) ? sh[t - o] : 0;
        __syncthreads();
        sh[t] += u;
        __syncthreads();
    }
    if (t < NB_SCAN) g_boff[t] = sh[t] - v;
    if (t == 255) g_rowptr[Nn] = sh[255];
}

__global__ void k_scan3() {
    int i = blockIdx.x * 256 + threadIdx.x;
    if (i < Nn) g_rowptr[i] += g_boff[blockIdx.x];
}

// scatter psrc + permute edge_attr into CSR order
__global__ void k_scatter(const int* __restrict__ ei, const float* __restrict__ eattr) {
    int e = blockIdx.x * blockDim.x + threadIdx.x;
    if (e >= Ee) return;
    int s = ei[e], d = ei[Ee + e];
    int pos = g_rowptr[d] + atomicAdd(&g_fill[d], 1);
    g_psrc[pos] = s;
    const float4* sp = (const float4*)(eattr + (size_t)e * EDIM);
    float4* dp = (float4*)(g_pattr + (size_t)pos * EDIM);
    dp[0] = sp[0]; dp[1] = sp[1]; dp[2] = sp[2]; dp[3] = sp[3];
}

// per-node mean of real in-edge attrs -> self-loop slot; psrc self = n
__global__ void __launch_bounds__(256) k_meanattr() {
    int n = (blockIdx.x * 256 + threadIdx.x) >> 5;
    int lane = threadIdx.x & 31;
    if (n >= Nn) return;
    int s0 = g_rowptr[n], s1 = g_rowptr[n + 1] - 1;   // real edges [s0,s1)
    float4 acc = make_float4(0.f, 0.f, 0.f, 0.f);
    const float4* pa = (const float4*)g_pattr;
    for (int r = s0 + (lane >> 2); r < s1; r += 8) {
        float4 v = pa[(size_t)r * 4 + (lane & 3)];
        acc.x += v.x; acc.y += v.y; acc.z += v.z; acc.w += v.w;
    }
#pragma unroll
    for (int o = 4; o < 32; o <<= 1) {
        acc.x += __shfl_xor_sync(0xffffffffu, acc.x, o);
        acc.y += __shfl_xor_sync(0xffffffffu, acc.y, o);
        acc.z += __shfl_xor_sync(0xffffffffu, acc.z, o);
        acc.w += __shfl_xor_sync(0xffffffffu, acc.w, o);
    }
    if (lane < 4) {
        float ic = 1.0f / fmaxf((float)(s1 - s0), 1.0f);
        acc.x *= ic; acc.y *= ic; acc.z *= ic; acc.w *= ic;
        ((float4*)g_pattr)[(size_t)s1 * 4 + lane] = acc;
    }
    if (lane == 0) g_psrc[s1] = n;
}

// ---------------- per-layer ----------------
// GEMM + fused score epilogue; 2-stage cp.async pipeline.
// Output stored as fp16 (gather-only consumer); scores from fp32 accumulators.
template <int K>
__global__ void __launch_bounds__(256, 3) k_gemm(const float* __restrict__ A,
                                                 const float* __restrict__ W,
                                                 const float* __restrict__ a_s,
                                                 const float* __restrict__ a_d,
                                                 __half* __restrict__ Out) {
    __shared__ float Ws[2][32][128];   // 32 KB
    __shared__ float Xs[2][64][32];    // 16 KB
    int tid = threadIdx.x;
    int tx = tid & 31, ty = tid >> 5;   // ty = 0..7
    int rowbase = blockIdx.x * 64;
    float4 acc[8];
#pragma unroll
    for (int r = 0; r < 8; r++) acc[r] = make_float4(0.f, 0.f, 0.f, 0.f);

    auto load_tiles = [&](int s, int kc) {
#pragma unroll
        for (int q = 0; q < 4; q++) {
            int idx = tid + 256 * q;
            int r = idx >> 5, c4 = idx & 31;
            cpa16((unsigned int)__cvta_generic_to_shared(&Ws[s][r][c4 * 4]),
                  &W[(size_t)(kc + r) * HC + c4 * 4], 16);
        }
#pragma unroll
        for (int q = 0; q < 2; q++) {
            int idx = tid + 256 * q;
            int r = idx >> 3, c4 = idx & 7;
            int row = rowbase + r;
            int ok = (row < Nn) ? 16 : 0;
            int rowc = (row < Nn) ? row : 0;
            cpa16((unsigned int)__cvta_generic_to_shared(&Xs[s][r][c4 * 4]),
                  &A[(size_t)rowc * K + kc + c4 * 4], ok);
        }
    };

    constexpr int NIT = K / 32;
    load_tiles(0, 0);
    asm volatile("cp.async.commit_group;" ::: "memory");

#pragma unroll
    for (int it = 0; it < NIT; it++) {
        int buf = it & 1;
        if (it + 1 < NIT) {
            load_tiles(buf ^ 1, (it + 1) * 32);
            asm volatile("cp.async.commit_group;" ::: "memory");
            asm volatile("cp.async.wait_group 1;" ::: "memory");
        } else {
            asm volatile("cp.async.wait_group 0;" ::: "memory");
        }
        __syncthreads();
#pragma unroll
        for (int k4 = 0; k4 < 32; k4 += 4) {
            float4 a4[8];
#pragma unroll
            for (int r = 0; r < 8; r++) a4[r] = *(const float4*)&Xs[buf][ty * 8 + r][k4];
#pragma unroll
            for (int kk = 0; kk < 4; kk++) {
                float4 b4 = *(const float4*)&Ws[buf][k4 + kk][tx * 4];
#pragma unroll
                for (int r = 0; r < 8; r++) {
                    float a = (kk == 0) ? a4[r].x : (kk == 1) ? a4[r].y : (kk == 2) ? a4[r].z : a4[r].w;
                    acc[r].x += a * b4.x;
                    acc[r].y += a * b4.y;
                    acc[r].z += a * b4.z;
                    acc[r].w += a * b4.w;
                }
            }
        }
        __syncthreads();
    }

    float4 as4 = *(const float4*)&a_s[tx * 4];
    float4 ad4 = *(const float4*)&a_d[tx * 4];
    int head = tx >> 3;

#pragma unroll
    for (int r = 0; r < 8; r++) {
        int row = rowbase + ty * 8 + r;
        if (row < Nn) {
            __half2 p01 = __floats2half2_rn(acc[r].x, acc[r].y);
            __half2 p23 = __floats2half2_rn(acc[r].z, acc[r].w);
            uint2 u;
            u.x = *reinterpret_cast<unsigned int*>(&p01);
            u.y = *reinterpret_cast<unsigned int*>(&p23);
            *(uint2*)&Out[(size_t)row * HC + tx * 4] = u;
            float ps = acc[r].x * as4.x + acc[r].y * as4.y + acc[r].z * as4.z + acc[r].w * as4.w;
            float pd = acc[r].x * ad4.x + acc[r].y * ad4.y + acc[r].z * ad4.z + acc[r].w * ad4.w;
#pragma unroll
            for (int o = 1; o < 8; o <<= 1) {
                ps += __shfl_xor_sync(0xffffffffu, ps, o);
                pd += __shfl_xor_sync(0xffffffffu, pd, o);
            }
            if ((tx & 7) == 0) {
                g_scs[row * 4 + head] = ps;
                g_scd[row * 4 + head] = pd;
            }
        }
    }
}

// ALL THREE layers' edge scores in one pass over pattr (read 54MB once, not 3x)
__global__ void k_sce3(const float* __restrict__ We0, const float* __restrict__ ae0,
                       const float* __restrict__ We1, const float* __restrict__ ae1,
                       const float* __restrict__ We2, const float* __restrict__ ae2) {
    __shared__ float ve[3][EDIM * Hh];
    int t = threadIdx.x;
    if (t < 3 * EDIM * Hh) {
        int l = t >> 6, u = t & 63;
        int d = u >> 2, h = u & 3;
        const float* We = (l == 0) ? We0 : (l == 1) ? We1 : We2;
        const float* ae = (l == 0) ? ae0 : (l == 1) ? ae1 : ae2;
        float s = 0.f;
#pragma unroll
        for (int c = 0; c < Cc; c++) s += We[d * HC + h * Cc + c] * ae[h * Cc + c];
        ve[l][u] = s;
    }
    __syncthreads();
    int i = blockIdx.x * blockDim.x + threadIdx.x;
    if (i >= EF) return;
    const float* ap = g_pattr + (size_t)i * EDIM;
    float4 av[4];
#pragma unroll
    for (int q = 0; q < 4; q++) av[q] = *(const float4*)(ap + q * 4);
#pragma unroll
    for (int l = 0; l < 3; l++) {
        const float* v = ve[l];
        float h0 = 0.f, h1 = 0.f, h2 = 0.f, h3 = 0.f;
#pragma unroll
        for (int q = 0; q < 4; q++) {
            int d = q * 4;
            h0 += av[q].x * v[d * 4 + 0] + av[q].y * v[(d + 1) * 4 + 0] + av[q].z * v[(d + 2) * 4 + 0] + av[q].w * v[(d + 3) * 4 + 0];
            h1 += av[q].x * v[d * 4 + 1] + av[q].y * v[(d + 1) * 4 + 1] + av[q].z * v[(d + 2) * 4 + 1] + av[q].w * v[(d + 3) * 4 + 1];
            h2 += av[q].x * v[d * 4 + 2] + av[q].y * v[(d + 1) * 4 + 2] + av[q].z * v[(d + 2) * 4 + 2] + av[q].w * v[(d + 3) * 4 + 2];
            h3 += av[q].x * v[d * 4 + 3] + av[q].y * v[(d + 1) * 4 + 3] + av[q].z * v[(d + 2) * 4 + 3] + av[q].w * v[(d + 3) * 4 + 3];
        }
        *(float4*)(g_sce + ((size_t)l * EF + i) * 4) = make_float4(h0, h1, h2, h3);
    }
}

// pick this lane's head weight from edge j's float4 weights (deg>32 fallback)
__device__ __forceinline__ float head_w(float4 wv, int j, int lane) {
    float wx = __shfl_sync(0xffffffffu, wv.x, j);
    float wy = __shfl_sync(0xffffffffu, wv.y, j);
    float wz = __shfl_sync(0xffffffffu, wv.z, j);
    float ww = __shfl_sync(0xffffffffu, wv.w, j);
    return lane < 16 ? (lane < 8 ? wx : wy) : (lane < 24 ? wz : ww);
}

// shared-staged gather from fp16 xw, MLP-8 unrolled
__device__ __forceinline__ void gather_unroll(const __half* __restrict__ xw,
                                              const int* __restrict__ ssrc,
                                              const float (*sw)[4],
                                              int deg, int lane, int c, float4& acc) {
    int j = 0;
    for (; j + 8 <= deg; j += 8) {
        int   sj[8]; float wj[8]; float4 xv[8];
#pragma unroll
        for (int q = 0; q < 8; q++) { sj[q] = ssrc[j + q]; wj[q] = sw[j + q][c]; }
#pragma unroll
        for (int q = 0; q < 8; q++) xv[q] = half4_load(xw + (size_t)sj[q] * HC + lane * 4);
#pragma unroll
        for (int q = 0; q < 8; q++) {
            acc.x += wj[q] * xv[q].x;
            acc.y += wj[q] * xv[q].y;
            acc.z += wj[q] * xv[q].z;
            acc.w += wj[q] * xv[q].w;
        }
    }
    for (; j + 4 <= deg; j += 4) {
        int   sj[4]; float wj[4]; float4 xv[4];
#pragma unroll
        for (int q = 0; q < 4; q++) { sj[q] = ssrc[j + q]; wj[q] = sw[j + q][c]; }
#pragma unroll
        for (int q = 0; q < 4; q++) xv[q] = half4_load(xw + (size_t)sj[q] * HC + lane * 4);
#pragma unroll
        for (int q = 0; q < 4; q++) {
            acc.x += wj[q] * xv[q].x;
            acc.y += wj[q] * xv[q].y;
            acc.z += wj[q] * xv[q].z;
            acc.w += wj[q] * xv[q].w;
        }
    }
    for (; j < deg; j++) {
        int sj = ssrc[j];
        float wj = sw[j][c];
        float4 xr = half4_load(xw + (size_t)sj * HC + lane * 4);
        acc.x += wj * xr.x;
        acc.y += wj * xr.y;
        acc.z += wj * xr.z;
        acc.w += wj * xr.w;
    }
}

// latency-bound kernel: force >=6 blocks/SM (48 warps) via reg cap
__global__ void __launch_bounds__(256, 6) k_agg(const __half* __restrict__ xw,
                                                const float* __restrict__ sce,
                                                const float* __restrict__ bias,
                                                float* __restrict__ hout) {
    __shared__ int   s_src[8][32];
    __shared__ float s_w[8][32][4];
    int wid = threadIdx.x >> 5;
    int n = (blockIdx.x * 256 + threadIdx.x) >> 5;
    int lane = threadIdx.x & 31;
    if (n >= Nn) return;
    int s0 = g_rowptr[n], s1 = g_rowptr[n + 1];
    int deg = s1 - s0;
    float4 sd = *(const float4*)(g_scd + n * 4);
    float4 acc = make_float4(0.f, 0.f, 0.f, 0.f);

    if (deg <= 32) {
        int e = s0 + lane;
        bool v = e < s1;
        int srcv = 0;
        float4 raw = make_float4(-FLT_MAX, -FLT_MAX, -FLT_MAX, -FLT_MAX);
        if (v) {
            srcv = g_psrc[e];
            raw = raw_score(sce, srcv, e, sd);
        }
        float4 m = wmax4(raw);
        float4 a = make_float4(0.f, 0.f, 0.f, 0.f);
        if (v) {
            a.x = __expf(raw.x - m.x);
            a.y = __expf(raw.y - m.y);
            a.z = __expf(raw.z - m.z);
            a.w = __expf(raw.w - m.w);
        }
        float4 s = wsum4(a);
        s_src[wid][lane] = srcv;
        s_w[wid][lane][0] = a.x / (s.x + 1e-16f);
        s_w[wid][lane][1] = a.y / (s.y + 1e-16f);
        s_w[wid][lane][2] = a.z / (s.z + 1e-16f);
        s_w[wid][lane][3] = a.w / (s.w + 1e-16f);
        __syncwarp();
        gather_unroll(xw, s_src[wid], s_w[wid], deg, lane, lane >> 3, acc);
    } else {
        float4 pm = make_float4(-FLT_MAX, -FLT_MAX, -FLT_MAX, -FLT_MAX);
        for (int base = s0; base < s1; base += 32) {
            int e = base + lane;
            if (e < s1) {
                float4 raw = raw_score(sce, g_psrc[e], e, sd);
                pm.x = fmaxf(pm.x, raw.x); pm.y = fmaxf(pm.y, raw.y);
                pm.z = fmaxf(pm.z, raw.z); pm.w = fmaxf(pm.w, raw.w);
            }
        }
        float4 m = wmax4(pm);
        float4 ps = make_float4(0.f, 0.f, 0.f, 0.f);
        for (int base = s0; base < s1; base += 32) {
            int e = base + lane;
            if (e < s1) {
                float4 raw = raw_score(sce, g_psrc[e], e, sd);
                ps.x += __expf(raw.x - m.x);
                ps.y += __expf(raw.y - m.y);
                ps.z += __expf(raw.z - m.z);
                ps.w += __expf(raw.w - m.w);
            }
        }
        float4 s = wsum4(ps);
        float4 rinv;
        rinv.x = 1.f / (s.x + 1e-16f);
        rinv.y = 1.f / (s.y + 1e-16f);
        rinv.z = 1.f / (s.z + 1e-16f);
        rinv.w = 1.f / (s.w + 1e-16f);
        for (int base = s0; base < s1; base += 32) {
            int e = base + lane;
            int sv = 0;
            float4 wv = make_float4(0.f, 0.f, 0.f, 0.f);
            if (e < s1) {
                sv = g_psrc[e];
                float4 raw = raw_score(sce, sv, e, sd);
                wv.x = __expf(raw.x - m.x) * rinv.x;
                wv.y = __expf(raw.y - m.y) * rinv.y;
                wv.z = __expf(raw.z - m.z) * rinv.z;
                wv.w = __expf(raw.w - m.w) * rinv.w;
            }
            int c2 = s1 - base; if (c2 > 32) c2 = 32;
            for (int j = 0; j < c2; j++) {
                int sj = __shfl_sync(0xffffffffu, sv, j);
                float wsel = head_w(wv, j, lane);
                float4 xr = half4_load(xw + (size_t)sj * HC + lane * 4);
                acc.x += wsel * xr.x;
                acc.y += wsel * xr.y;
                acc.z += wsel * xr.z;
                acc.w += wsel * xr.w;
            }
        }
    }
    float4 b4 = *(const float4*)(bias + lane * 4);
    float4 o4;
    o4.x = fmaxf(acc.x + b4.x, 0.f);
    o4.y = fmaxf(acc.y + b4.y, 0.f);
    o4.z = fmaxf(acc.z + b4.z, 0.f);
    o4.w = fmaxf(acc.w + b4.w, 0.f);
    *(float4*)(hout + (size_t)n * HC + lane * 4) = o4;
}

// ---------------- output head ----------------
__global__ void __launch_bounds__(128) k_pool(const float* __restrict__ h,
                                              const int* __restrict__ batch) {
    int t = threadIdx.x;
    int n0 = blockIdx.x * 64;
    int nend = n0 + 64; if (nend > Nn) nend = Nn;
    float acc = 0.f;
    int cnt = 0;
    int curb = batch[n0];
    for (int n = n0; n < nend; n++) {
        int b = batch[n];
        if (b != curb) {
            atomicAdd(&g_gsum[curb * HC + t], acc);
            if (t == 0) atomicAdd(&g_gcnt[curb], cnt);
            curb = b; acc = 0.f; cnt = 0;
        }
        acc += h[(size_t)n * HC + t];
        cnt++;
    }
    atomicAdd(&g_gsum[curb * HC + t], acc);
    if (t == 0) atomicAdd(&g_gcnt[curb], cnt);
}

__global__ void k_head(const float* __restrict__ Wl, const float* __restrict__ bl,
                       float* __restrict__ out) {
    int tid = threadIdx.x;
    if (tid >= Bb * Aa) return;
    int b = tid >> 3, a = tid & 7;
    float ic = 1.0f / fmaxf((float)g_gcnt[b], 1.0f);
    float s = 0.f;
    for (int c = 0; c < HC; c++) s += g_gsum[b * HC + c] * Wl[c * Aa + a];
    out[tid] = tanhf(s * ic + bl[a]);
}

// ---------------- launch ----------------
extern "C" void kernel_launch(void* const* d_in, const int* in_sizes, int n_in,
                              void* d_out, int out_size) {
    const float* slots[22];
    int k = 0;
    const int* ei = nullptr;
    const int* batch = nullptr;
    for (int i = 0; i < n_in; i++) {
        int sz = in_sizes[i];
        if (sz == 2 * Ee) ei = (const int*)d_in[i];
        else if (sz == Nn) batch = (const int*)d_in[i];
        else if (k < 22) slots[k++] = (const float*)d_in[i];
    }
    const float* x      = slots[0];
    const float* eattr  = slots[1];
    const float* W[3]   = { slots[2],  slots[8],  slots[14] };
    const float* We[3]  = { slots[3],  slots[9],  slots[15] };
    const float* aS[3]  = { slots[4],  slots[10], slots[16] };
    const float* aD[3]  = { slots[5],  slots[11], slots[17] };
    const float* aE[3]  = { slots[6],  slots[12], slots[18] };
    const float* bia[3] = { slots[7],  slots[13], slots[19] };
    const float* Wl = slots[20];
    const float* bl = slots[21];
    float* out = (float*)d_out;

    __half* p_xwh;
    float *p_hA, *p_hB, *p_sce;
    cudaGetSymbolAddress((void**)&p_xwh, g_xwh);
    cudaGetSymbolAddress((void**)&p_hA, g_hA);
    cudaGetSymbolAddress((void**)&p_hB, g_hB);
    cudaGetSymbolAddress((void**)&p_sce, g_sce);

    k_init<<<(Nn + 255) / 256, 256>>>();
    k_count<<<(Ee + 255) / 256, 256>>>(ei);
    k_scan1<<<NB_SCAN, 256>>>();
    // launch #4 -> profiled by the fixed ncu window
    k_gemm<64><<<(Nn + 63) / 64, 256>>>(x, W[0], aS[0], aD[0], p_xwh);
    k_scan2<<<1, 256>>>();
    k_scan3<<<NB_SCAN, 256>>>();
    k_scatter<<<(Ee + 255) / 256, 256>>>(ei, eattr);
    k_meanattr<<<(Nn * 32 + 255) / 256, 256>>>();
    k_sce3<<<(EF + 255) / 256, 256>>>(We[0], aE[0], We[1], aE[1], We[2], aE[2]);

    const float* hin = x;
    float* houts[3] = { p_hA, p_hB, p_hA };
    for (int l = 0; l < 3; l++) {
        if (l > 0) k_gemm<128><<<(Nn + 63) / 64, 256>>>(hin, W[l], aS[l], aD[l], p_xwh);
        k_agg<<<(Nn + 7) / 8, 256>>>(p_xwh, p_sce + (size_t)l * EF * Hh, bia[l], houts[l]);
        hin = houts[l];
    }

    k_pool<<<(Nn + 63) / 64, 128>>>(hin, batch);
    k_head<<<1, 512>>>(Wl, bl, out);
}